// round 1
// baseline (speedup 1.0000x reference)
#include <cuda_runtime.h>
#include <cuda_bf16.h>
#include <math.h>

#define BB 4
#define SEQ 8192
#define DIM 256
#define NH 8
#define HD 32
#define INTERNAL 256
#define QKVO 1024
// SCALE = HD^-0.5 = 2^-2.5 ; S = sqrt(SCALE/SEQ) = 2^-7.75
#define SCALE_F 0.17677669529663687f
#define S_CONST 0.00464534038f

// ---------------- scratch (static device allocations are allowed) -----------
__device__ float g_qkvo[(size_t)BB * SEQ * QKVO];   // 128 MB
__device__ float g_tmp[(size_t)BB * SEQ * DIM];     // 32 MB
__device__ float g_kv[BB * NH * HD * HD];           // kv_state
__device__ float g_km[BB * NH * HD];                // sum of kh over n
__device__ float g_vm[BB * NH * HD];                // sum of v over n

__device__ __forceinline__ float elu1(float x) {
    // elu(x)+1 : x>0 ? x+1 : exp(x)
    return x > 0.f ? x + 1.f : __expf(x) * 0.f + expf(x);
}

// ---------------- SGEMM: C[M,Nn] = A[M,K] @ W[Nn,K]^T + bias ----------------
__global__ __launch_bounds__(256, 2)
void sgemm_nt(const float* __restrict__ A, const float* __restrict__ W,
              const float* __restrict__ bias, float* __restrict__ C,
              int M, int Nn, int K) {
    __shared__ __align__(16) float As[8][128];
    __shared__ __align__(16) float Bs[8][128];
    const int tid = threadIdx.x;
    const int bm = blockIdx.y * 128;
    const int bn = blockIdx.x * 128;
    const int lr = tid >> 1;            // row within tile 0..127
    const int lk = (tid & 1) << 2;      // 0 or 4
    const float* Aptr = A + (size_t)(bm + lr) * K + lk;
    const float* Wptr = W + (size_t)(bn + lr) * K + lk;
    const int tx = (tid & 15) << 3;     // 0..120
    const int ty = (tid >> 4) << 3;     // 0..120
    float acc[8][8];
#pragma unroll
    for (int i = 0; i < 8; i++)
#pragma unroll
        for (int j = 0; j < 8; j++) acc[i][j] = 0.f;

    for (int k0 = 0; k0 < K; k0 += 8) {
        float4 a4 = *(const float4*)(Aptr + k0);
        float4 b4 = *(const float4*)(Wptr + k0);
        __syncthreads();
        As[lk + 0][lr] = a4.x; As[lk + 1][lr] = a4.y;
        As[lk + 2][lr] = a4.z; As[lk + 3][lr] = a4.w;
        Bs[lk + 0][lr] = b4.x; Bs[lk + 1][lr] = b4.y;
        Bs[lk + 2][lr] = b4.z; Bs[lk + 3][lr] = b4.w;
        __syncthreads();
#pragma unroll
        for (int kk = 0; kk < 8; kk++) {
            float ra[8], rb[8];
            *(float4*)(ra)     = *(const float4*)(&As[kk][ty]);
            *(float4*)(ra + 4) = *(const float4*)(&As[kk][ty + 4]);
            *(float4*)(rb)     = *(const float4*)(&Bs[kk][tx]);
            *(float4*)(rb + 4) = *(const float4*)(&Bs[kk][tx + 4]);
#pragma unroll
            for (int i = 0; i < 8; i++)
#pragma unroll
                for (int j = 0; j < 8; j++)
                    acc[i][j] += ra[i] * rb[j];
        }
    }
#pragma unroll
    for (int i = 0; i < 8; i++) {
        const size_t row = (size_t)(bm + ty + i) * Nn + bn + tx;
#pragma unroll
        for (int j = 0; j < 8; j += 4) {
            float4 o;
            o.x = acc[i][j + 0] + bias[bn + tx + j + 0];
            o.y = acc[i][j + 1] + bias[bn + tx + j + 1];
            o.z = acc[i][j + 2] + bias[bn + tx + j + 2];
            o.w = acc[i][j + 3] + bias[bn + tx + j + 3];
            *(float4*)(C + row + j) = o;
        }
    }
}

// ---------------- zero the state accumulators ----------------
__global__ void zero_kernel() {
    int i = blockIdx.x * 256 + threadIdx.x;
    if (i < BB * NH * HD * HD) g_kv[i] = 0.f;
    if (i < BB * NH * HD) { g_km[i] = 0.f; g_vm[i] = 0.f; }
}

// ---------------- per-(b,h) state reduction over N ----------------
#define CHUNK 512
__global__ __launch_bounds__(256)
void reduce_kernel(const float* __restrict__ sinp, const float* __restrict__ cosp) {
    const int bh = blockIdx.x;              // 0..31
    const int chunk = blockIdx.y;           // 0..15
    const int b = bh / NH, h = bh % NH;
    const int tid = threadIdx.x;
    const int j = tid >> 5;                 // token sub 0..7
    const int d = tid & 31;
    const int e = d;
    const int dbase = j * 4;
    __shared__ float s_ks[8][32];
    __shared__ float s_vs[8][32];
    float acc[4] = {0.f, 0.f, 0.f, 0.f};
    float ksum = 0.f, vsum = 0.f;
    const int n0 = chunk * CHUNK;
    const float sgn = (d & 1) ? 1.f : -1.f;

    for (int nb = 0; nb < CHUNK; nb += 8) {
        const int n = n0 + nb + j;
        const size_t row = ((size_t)b * SEQ + n) * QKVO;
        const float kval  = g_qkvo[row + INTERNAL + h * HD + d];
        const float kpair = g_qkvo[row + INTERNAL + h * HD + (d ^ 1)];
        const float vval  = g_qkvo[row + 2 * INTERNAL + h * HD + d];
        const float kh  = elu1(kval);
        const float khp = elu1(kpair);
        const float sn = sinp[n * HD + d];
        const float cs = cosp[n * HD + d];
        const float ks = kh * cs + sgn * khp * sn;
        __syncthreads();
        s_ks[j][d] = ks * S_CONST;
        s_vs[j][d] = vval * S_CONST;
        ksum += kh;
        vsum += vval;
        __syncthreads();
#pragma unroll
        for (int jj = 0; jj < 8; jj++) {
            const float vv = s_vs[jj][e];
#pragma unroll
            for (int dd = 0; dd < 4; dd++)
                acc[dd] += s_ks[jj][dbase + dd] * vv;
        }
    }
#pragma unroll
    for (int dd = 0; dd < 4; dd++)
        atomicAdd(&g_kv[(bh * HD + dbase + dd) * HD + e], acc[dd]);
    atomicAdd(&g_km[bh * HD + d], ksum);
    atomicAdd(&g_vm[bh * HD + d], vsum);
}

// ---------------- per-token attention epilogue + lepe + o-gate ----------------
#define TB 64
__global__ __launch_bounds__(256)
void attn_kernel(const float* __restrict__ sinp, const float* __restrict__ cosp,
                 const float* __restrict__ W_lepe, const float* __restrict__ b_lepe) {
    const int b = blockIdx.y;
    const int n0 = blockIdx.x * TB;
    const int h = threadIdx.x >> 5;
    const int lane = threadIdx.x & 31;
    __shared__ float s_kv[NH][HD][HD];      // 32 KB
    __shared__ float s_km[NH * HD], s_vm[NH * HD];
    for (int i = threadIdx.x; i < NH * HD * HD; i += 256)
        ((float*)s_kv)[i] = g_kv[b * NH * HD * HD + i];
    const float invN = 1.f / (float)SEQ;
    for (int i = threadIdx.x; i < NH * HD; i += 256) {
        s_km[i] = g_km[b * NH * HD + i] * invN;
        s_vm[i] = g_vm[b * NH * HD + i] * invN;
    }
    __syncthreads();

    const float km = s_km[h * HD + lane];
    const float vm = s_vm[h * HD + lane];
    const float sgn = (lane & 1) ? 1.f : -1.f;
    const int c = h * HD + lane;
    const float w0 = W_lepe[c * 3 + 0];
    const float w1 = W_lepe[c * 3 + 1];
    const float w2 = W_lepe[c * 3 + 2];
    const float bl = b_lepe[c];

    for (int t = 0; t < TB; t++) {
        const int n = n0 + t;
        const size_t row = ((size_t)b * SEQ + n) * QKVO;
        const float q = g_qkvo[row + c];
        const float qh = elu1(q);
        // z = SCALE * dot(qh, kmean)
        float zv = qh * km;
#pragma unroll
        for (int off = 16; off; off >>= 1) zv += __shfl_xor_sync(0xffffffffu, zv, off);
        const float z = zv * SCALE_F;
        // theta shift of qh
        const float qhp = __shfl_xor_sync(0xffffffffu, qh, 1);
        const float sn = sinp[n * HD + lane];
        const float cs = cosp[n * HD + lane];
        const float qs = qh * cs + sgn * qhp * sn;
        // attn_out[e] = sum_d qs[d] * kv[d][e]
        float acc = 0.f;
#pragma unroll
        for (int dd = 0; dd < HD; dd++) {
            const float qsd = __shfl_sync(0xffffffffu, qs, dd);
            acc += qsd * s_kv[h][dd][lane];
        }
        const float res = acc * (1.f + 1.f / (z + 1e-6f)) - z * vm;
        // lepe depthwise conv (padding 1)
        const float v0 = g_qkvo[row + 2 * INTERNAL + c];
        const float vmm = (n > 0)       ? g_qkvo[row - QKVO + 2 * INTERNAL + c] : 0.f;
        const float vpp = (n < SEQ - 1) ? g_qkvo[row + QKVO + 2 * INTERNAL + c] : 0.f;
        const float lepe = vmm * w0 + v0 * w1 + vpp * w2 + bl;
        const float og = g_qkvo[row + 3 * INTERNAL + c];
        g_tmp[((size_t)b * SEQ + n) * DIM + c] = (res + lepe) * og;
    }
}

// ---------------- launch ----------------
extern "C" void kernel_launch(void* const* d_in, const int* in_sizes, int n_in,
                              void* d_out, int out_size) {
    const float* x      = (const float*)d_in[0];
    const float* sinp   = (const float*)d_in[1];
    const float* cosp   = (const float*)d_in[2];
    const float* W_qkvo = (const float*)d_in[3];
    const float* b_qkvo = (const float*)d_in[4];
    const float* W_lepe = (const float*)d_in[5];
    const float* b_lepe = (const float*)d_in[6];
    const float* W_proj = (const float*)d_in[7];
    const float* b_proj = (const float*)d_in[8];
    float* out = (float*)d_out;

    float *qkvo_p, *tmp_p;
    cudaGetSymbolAddress((void**)&qkvo_p, g_qkvo);
    cudaGetSymbolAddress((void**)&tmp_p, g_tmp);

    const int M = BB * SEQ;  // 32768

    // 1) qkvo = x @ W_qkvo^T + b_qkvo
    {
        dim3 grid(QKVO / 128, M / 128);
        sgemm_nt<<<grid, 256>>>(x, W_qkvo, b_qkvo, qkvo_p, M, QKVO, DIM);
    }
    // 2) zero accumulators
    zero_kernel<<<(BB * NH * HD * HD + 255) / 256, 256>>>();
    // 3) state reduction
    {
        dim3 grid(BB * NH, SEQ / CHUNK);
        reduce_kernel<<<grid, 256>>>(sinp, cosp);
    }
    // 4) attention epilogue
    {
        dim3 grid(SEQ / TB, BB);
        attn_kernel<<<grid, 256>>>(sinp, cosp, W_lepe, b_lepe);
    }
    // 5) out = tmp @ W_proj^T + b_proj
    {
        dim3 grid(DIM / 128, M / 128);
        sgemm_nt<<<grid, 256>>>(tmp_p, W_proj, b_proj, out, M, DIM, DIM);
    }
}

// round 3
// speedup vs baseline: 1.9160x; 1.9160x over previous
#include <cuda_runtime.h>
#include <cuda_fp16.h>
#include <math.h>
#include <stdint.h>

#define BB 4
#define SEQ 8192
#define DIM 256
#define NH 8
#define HD 32
#define INTERNAL 256
#define QKVO 1024
#define KK 512                      // split K (2 x 256)
#define SCALE_F 0.17677669529663687f
#define S_CONST 0.00464534038f

// ---------------- scratch ----------------
__device__ __align__(16) float g_qkvo[(size_t)BB * SEQ * QKVO];      // 128 MB
__device__ __align__(16) __half g_xs[(size_t)BB * SEQ * KK];         // 32 MB
__device__ __align__(16) __half g_ws[(size_t)QKVO * KK];             // 1 MB
__device__ __align__(16) __half g_tmph[(size_t)BB * SEQ * KK];       // 32 MB
__device__ __align__(16) __half g_wp[(size_t)DIM * KK];              // 256 KB
__device__ float g_kv[BB * NH * HD * HD];
__device__ float g_km[BB * NH * HD];
__device__ float g_vm[BB * NH * HD];

__device__ __forceinline__ float elu1(float x) { return x > 0.f ? x + 1.f : expf(x); }

__device__ __forceinline__ uint32_t smem_u32(const void* p) {
    return (uint32_t)__cvta_generic_to_shared(p);
}
__device__ __forceinline__ void cpa16(uint32_t dst, const void* src) {
    asm volatile("cp.async.cg.shared.global [%0], [%1], 16;" :: "r"(dst), "l"(src));
}
__device__ __forceinline__ void cpa_commit() {
    asm volatile("cp.async.commit_group;" ::: "memory");
}
template <int N> __device__ __forceinline__ void cpa_wait() {
    asm volatile("cp.async.wait_group %0;" :: "n"(N) : "memory");
}
#define LDSM4(r, a) \
    asm volatile("ldmatrix.sync.aligned.m8n8.x4.shared.b16 {%0,%1,%2,%3}, [%4];" \
                 : "=r"((r)[0]), "=r"((r)[1]), "=r"((r)[2]), "=r"((r)[3]) : "r"(a))
#define MMA16816(d, a, b0, b1) \
    asm volatile("mma.sync.aligned.m16n8k16.row.col.f32.f16.f16.f32 " \
                 "{%0,%1,%2,%3},{%4,%5,%6,%7},{%8,%9},{%0,%1,%2,%3};" \
                 : "+f"((d)[0]), "+f"((d)[1]), "+f"((d)[2]), "+f"((d)[3]) \
                 : "r"((a)[0]), "r"((a)[1]), "r"((a)[2]), "r"((a)[3]), "r"(b0), "r"(b1))

// ---------------- GEMM config ----------------
#define BM 128
#define BN 128
#define BK 64                       // fp16 elems per chunk (128 B per row)
#define NCH (KK / BK)               // 8
#define NSTG 3
#define TILEB (BM * 128)            // 16384 B per operand tile
#define STGB (2 * TILEB)            // 32768 B per stage
#define GEMM_SMEM (NSTG * STGB)     // 98304 B

// stage one K-chunk of A and B tiles into smem buffer `buf` (swizzled)
__device__ __forceinline__ void stage_tiles(uint32_t sb, const __half* Ab,
                                            const __half* Bb, int tid,
                                            int chunk, int buf) {
    const uint32_t ab = sb + buf * STGB;
    const uint32_t bbse = ab + TILEB;
    const __half* Ap = Ab + chunk * BK;
    const __half* Bp = Bb + chunk * BK;
#pragma unroll
    for (int i = 0; i < 4; i++) {
        int line = tid + i * 256;            // 0..1023
        int row = line >> 3, j = line & 7;   // 16B granule
        uint32_t sw = row * 128 + ((j ^ (row & 7)) << 4);
        cpa16(ab + sw, Ap + (size_t)row * KK + j * 8);
    }
#pragma unroll
    for (int i = 0; i < 4; i++) {
        int line = tid + i * 256;
        int row = line >> 3, j = line & 7;
        uint32_t sw = row * 128 + ((j ^ (row & 7)) << 4);
        cpa16(bbse + sw, Bp + (size_t)row * KK + j * 8);
    }
    cpa_commit();
}

// C[M,Nn] = A'[M,512]h @ B'[Nn,512]h^T + bias (fp32 accum)
__global__ __launch_bounds__(256, 1)
void gemm_half(const __half* __restrict__ A, const __half* __restrict__ Bm,
               const float* __restrict__ bias, float* __restrict__ C, int Nn) {
    extern __shared__ char smem[];
    const uint32_t sb = smem_u32(smem);
    const int tid = threadIdx.x;
    const int wid = tid >> 5;
    const int lane = tid & 31;
    const int bm = blockIdx.y * BM;
    const int bn = blockIdx.x * BN;
    const int wm0 = (wid & 1) * 64;          // warp M offset
    const int wn0 = (wid >> 1) * 32;         // warp N offset

    const __half* Ab = A + (size_t)bm * KK;
    const __half* Bb = Bm + (size_t)bn * KK;

    float acc[4][4][4];
#pragma unroll
    for (int i = 0; i < 4; i++)
#pragma unroll
        for (int j = 0; j < 4; j++)
#pragma unroll
            for (int k = 0; k < 4; k++) acc[i][j][k] = 0.f;

    // ldmatrix lane->row/col components
    const int lrA = (lane & 7) + ((lane >> 3) & 1) * 8;   // row in m16 tile
    const int lcA = ((lane >> 4) & 1) * 16;               // 0 / 16 bytes (k half)
    const int lrB = ((lane >> 4) & 1) * 8 + (lane & 7);   // row in n16 group
    const int lcB = ((lane >> 3) & 1) * 16;

    stage_tiles(sb, Ab, Bb, tid, 0, 0);
    stage_tiles(sb, Ab, Bb, tid, 1, 1);

    for (int c = 0; c < NCH; c++) {
        if (c + 2 < NCH) cpa_wait<1>(); else cpa_wait<0>();
        __syncthreads();
        if (c + 2 < NCH) stage_tiles(sb, Ab, Bb, tid, c + 2, (c + 2) % NSTG);
        const uint32_t ab = sb + (c % NSTG) * STGB;
        const uint32_t bbse = ab + TILEB;
#pragma unroll
        for (int ks = 0; ks < 4; ks++) {
            uint32_t afr[4][4], bfr[2][4];
#pragma unroll
            for (int mi = 0; mi < 4; mi++) {
                int r = wm0 + mi * 16 + lrA;
                uint32_t cc = (uint32_t)(ks * 32 + lcA);
                LDSM4(afr[mi], ab + r * 128 + (cc ^ ((r & 7) << 4)));
            }
#pragma unroll
            for (int bi = 0; bi < 2; bi++) {
                int r = wn0 + bi * 16 + lrB;
                uint32_t cc = (uint32_t)(ks * 32 + lcB);
                LDSM4(bfr[bi], bbse + r * 128 + (cc ^ ((r & 7) << 4)));
            }
#pragma unroll
            for (int mi = 0; mi < 4; mi++)
#pragma unroll
                for (int nj = 0; nj < 4; nj++)
                    MMA16816(acc[mi][nj], afr[mi],
                             bfr[nj >> 1][(nj & 1) * 2], bfr[nj >> 1][(nj & 1) * 2 + 1]);
        }
    }

    // epilogue: direct float2 stores + bias
    const int g = lane >> 2, t4 = lane & 3;
#pragma unroll
    for (int mi = 0; mi < 4; mi++) {
#pragma unroll
        for (int nj = 0; nj < 4; nj++) {
            const int col = bn + wn0 + nj * 8 + t4 * 2;
            const float2 bv = *(const float2*)(bias + col);
            const int row0 = bm + wm0 + mi * 16 + g;
            float2 o0 = {acc[mi][nj][0] + bv.x, acc[mi][nj][1] + bv.y};
            float2 o1 = {acc[mi][nj][2] + bv.x, acc[mi][nj][3] + bv.y};
            *(float2*)(C + (size_t)row0 * Nn + col) = o0;
            *(float2*)(C + (size_t)(row0 + 8) * Nn + col) = o1;
        }
    }
}

// ---------------- fp16 hi/lo split: [R,256]f32 -> [R,512]h ----------------
// mode 0 (A operand): [hi | lo]    mode 1 (B operand): [hi | hi]
__global__ void split_half(const float* __restrict__ in, __half* __restrict__ out,
                           int total, int mode) {
    int i = blockIdx.x * 256 + threadIdx.x;
    if (i >= total) return;
    int row = i >> 8, c = i & 255;
    float v = in[i];
    __half hi = __float2half_rn(v);
    __half lo = __float2half_rn(v - __half2float(hi));
    size_t base = (size_t)row * KK + c;
    out[base] = hi;
    out[base + 256] = (mode == 0) ? lo : hi;
}

// ---------------- zero state accumulators ----------------
__global__ void zero_kernel() {
    int i = blockIdx.x * 256 + threadIdx.x;
    if (i < BB * NH * HD * HD) g_kv[i] = 0.f;
    if (i < BB * NH * HD) { g_km[i] = 0.f; g_vm[i] = 0.f; }
}

// ---------------- per-(b,h) state reduction over N ----------------
#define CHUNK 512
__global__ __launch_bounds__(256)
void reduce_kernel(const float* __restrict__ sinp, const float* __restrict__ cosp) {
    const int bh = blockIdx.x;
    const int chunk = blockIdx.y;
    const int b = bh / NH, h = bh % NH;
    const int tid = threadIdx.x;
    const int j = tid >> 5;
    const int d = tid & 31;
    const int e = d;
    const int dbase = j * 4;
    __shared__ float s_ks[8][32];
    __shared__ float s_vs[8][32];
    float acc[4] = {0.f, 0.f, 0.f, 0.f};
    float ksum = 0.f, vsum = 0.f;
    const int n0 = chunk * CHUNK;
    const float sgn = (d & 1) ? 1.f : -1.f;

    for (int nb = 0; nb < CHUNK; nb += 8) {
        const int n = n0 + nb + j;
        const size_t row = ((size_t)b * SEQ + n) * QKVO;
        const float kval  = g_qkvo[row + INTERNAL + h * HD + d];
        const float kpair = g_qkvo[row + INTERNAL + h * HD + (d ^ 1)];
        const float vval  = g_qkvo[row + 2 * INTERNAL + h * HD + d];
        const float kh  = elu1(kval);
        const float khp = elu1(kpair);
        const float sn = sinp[n * HD + d];
        const float cs = cosp[n * HD + d];
        const float ks = kh * cs + sgn * khp * sn;
        __syncthreads();
        s_ks[j][d] = ks * S_CONST;
        s_vs[j][d] = vval * S_CONST;
        ksum += kh;
        vsum += vval;
        __syncthreads();
#pragma unroll
        for (int jj = 0; jj < 8; jj++) {
            const float vv = s_vs[jj][e];
#pragma unroll
            for (int dd = 0; dd < 4; dd++)
                acc[dd] += s_ks[jj][dbase + dd] * vv;
        }
    }
#pragma unroll
    for (int dd = 0; dd < 4; dd++)
        atomicAdd(&g_kv[(bh * HD + dbase + dd) * HD + e], acc[dd]);
    atomicAdd(&g_km[bh * HD + d], ksum);
    atomicAdd(&g_vm[bh * HD + d], vsum);
}

// ---------------- per-token epilogue: emits fp16 hi/lo pair directly ----------------
#define TB 64
__global__ __launch_bounds__(256)
void attn_kernel(const float* __restrict__ sinp, const float* __restrict__ cosp,
                 const float* __restrict__ W_lepe, const float* __restrict__ b_lepe) {
    const int b = blockIdx.y;
    const int n0 = blockIdx.x * TB;
    const int h = threadIdx.x >> 5;
    const int lane = threadIdx.x & 31;
    __shared__ float s_kv[NH][HD][HD];
    __shared__ float s_km[NH * HD], s_vm[NH * HD];
    for (int i = threadIdx.x; i < NH * HD * HD; i += 256)
        ((float*)s_kv)[i] = g_kv[b * NH * HD * HD + i];
    const float invN = 1.f / (float)SEQ;
    for (int i = threadIdx.x; i < NH * HD; i += 256) {
        s_km[i] = g_km[b * NH * HD + i] * invN;
        s_vm[i] = g_vm[b * NH * HD + i] * invN;
    }
    __syncthreads();

    const float km = s_km[h * HD + lane];
    const float vm = s_vm[h * HD + lane];
    const float sgn = (lane & 1) ? 1.f : -1.f;
    const int c = h * HD + lane;
    const float w0 = W_lepe[c * 3 + 0];
    const float w1 = W_lepe[c * 3 + 1];
    const float w2 = W_lepe[c * 3 + 2];
    const float bl = b_lepe[c];

    for (int t = 0; t < TB; t++) {
        const int n = n0 + t;
        const size_t row = ((size_t)b * SEQ + n) * QKVO;
        const float q = g_qkvo[row + c];
        const float qh = elu1(q);
        float zv = qh * km;
#pragma unroll
        for (int off = 16; off; off >>= 1) zv += __shfl_xor_sync(0xffffffffu, zv, off);
        const float z = zv * SCALE_F;
        const float qhp = __shfl_xor_sync(0xffffffffu, qh, 1);
        const float sn = sinp[n * HD + lane];
        const float cs = cosp[n * HD + lane];
        const float qs = qh * cs + sgn * qhp * sn;
        float acc = 0.f;
#pragma unroll
        for (int dd = 0; dd < HD; dd++) {
            const float qsd = __shfl_sync(0xffffffffu, qs, dd);
            acc += qsd * s_kv[h][dd][lane];
        }
        const float res = acc * (1.f + 1.f / (z + 1e-6f)) - z * vm;
        const float v0 = g_qkvo[row + 2 * INTERNAL + c];
        const float vmm = (n > 0)       ? g_qkvo[row - QKVO + 2 * INTERNAL + c] : 0.f;
        const float vpp = (n < SEQ - 1) ? g_qkvo[row + QKVO + 2 * INTERNAL + c] : 0.f;
        const float lepe = vmm * w0 + v0 * w1 + vpp * w2 + bl;
        const float og = g_qkvo[row + 3 * INTERNAL + c];
        const float rres = (res + lepe) * og;
        __half hi = __float2half_rn(rres);
        __half lo = __float2half_rn(rres - __half2float(hi));
        const size_t ob = ((size_t)b * SEQ + n) * KK + c;
        g_tmph[ob] = hi;
        g_tmph[ob + 256] = lo;
    }
}

// ---------------- launch ----------------
extern "C" void kernel_launch(void* const* d_in, const int* in_sizes, int n_in,
                              void* d_out, int out_size) {
    const float* x      = (const float*)d_in[0];
    const float* sinp   = (const float*)d_in[1];
    const float* cosp   = (const float*)d_in[2];
    const float* W_qkvo = (const float*)d_in[3];
    const float* b_qkvo = (const float*)d_in[4];
    const float* W_lepe = (const float*)d_in[5];
    const float* b_lepe = (const float*)d_in[6];
    const float* W_proj = (const float*)d_in[7];
    const float* b_proj = (const float*)d_in[8];
    float* out = (float*)d_out;

    __half *xs_p, *ws_p, *tmph_p, *wp_p;
    float* qkvo_p;
    cudaGetSymbolAddress((void**)&qkvo_p, g_qkvo);
    cudaGetSymbolAddress((void**)&xs_p, g_xs);
    cudaGetSymbolAddress((void**)&ws_p, g_ws);
    cudaGetSymbolAddress((void**)&tmph_p, g_tmph);
    cudaGetSymbolAddress((void**)&wp_p, g_wp);

    cudaFuncSetAttribute(gemm_half, cudaFuncAttributeMaxDynamicSharedMemorySize, GEMM_SMEM);

    const int M = BB * SEQ;  // 32768

    // 0) fp16 hi/lo splits
    split_half<<<(M * DIM + 255) / 256, 256>>>(x, xs_p, M * DIM, 0);
    split_half<<<(QKVO * DIM + 255) / 256, 256>>>(W_qkvo, ws_p, QKVO * DIM, 1);
    split_half<<<(DIM * DIM + 255) / 256, 256>>>(W_proj, wp_p, DIM * DIM, 1);

    // 1) qkvo = x @ W_qkvo^T + b  (HMMA, K=512 split)
    {
        dim3 grid(QKVO / BN, M / BM);
        gemm_half<<<grid, 256, GEMM_SMEM>>>(xs_p, ws_p, b_qkvo, qkvo_p, QKVO);
    }
    // 2) zero accumulators
    zero_kernel<<<(BB * NH * HD * HD + 255) / 256, 256>>>();
    // 3) state reduction
    {
        dim3 grid(BB * NH, SEQ / CHUNK);
        reduce_kernel<<<grid, 256>>>(sinp, cosp);
    }
    // 4) attention epilogue (writes fp16 hi/lo)
    {
        dim3 grid(SEQ / TB, BB);
        attn_kernel<<<grid, 256>>>(sinp, cosp, W_lepe, b_lepe);
    }
    // 5) out = tmp @ W_proj^T + b_proj  (HMMA)
    {
        dim3 grid(DIM / BN, M / BM);
        gemm_half<<<grid, 256, GEMM_SMEM>>>(tmph_p, wp_p, b_proj, out, DIM);
    }
}

// round 4
// speedup vs baseline: 2.0802x; 1.0857x over previous
#include <cuda_runtime.h>
#include <cuda_fp16.h>
#include <math.h>
#include <stdint.h>

#define BB 4
#define SEQ 8192
#define DIM 256
#define NH 8
#define HD 32
#define INTERNAL 256
#define QKVO 1024
#define KK 512                      // split K (2 x 256)
#define SCALE_F 0.17677669529663687f
#define S_CONST 0.00464534038f

// ---------------- scratch ----------------
__device__ __align__(16) float g_qkvo[(size_t)BB * SEQ * QKVO];      // 128 MB
__device__ __align__(16) __half g_xs[(size_t)BB * SEQ * KK];         // 32 MB
__device__ __align__(16) __half g_ws[(size_t)QKVO * KK];             // 1 MB
__device__ __align__(16) __half g_tmph[(size_t)BB * SEQ * KK];       // 32 MB
__device__ __align__(16) __half g_wp[(size_t)DIM * KK];              // 256 KB
__device__ float g_kv[BB * NH * HD * HD];
__device__ float g_km[BB * NH * HD];
__device__ float g_vm[BB * NH * HD];

__device__ __forceinline__ float elu1(float x) { return x > 0.f ? x + 1.f : expf(x); }

__device__ __forceinline__ uint32_t smem_u32(const void* p) {
    return (uint32_t)__cvta_generic_to_shared(p);
}
__device__ __forceinline__ void cpa16(uint32_t dst, const void* src) {
    asm volatile("cp.async.cg.shared.global [%0], [%1], 16;" :: "r"(dst), "l"(src));
}
__device__ __forceinline__ void cpa_commit() {
    asm volatile("cp.async.commit_group;" ::: "memory");
}
template <int N> __device__ __forceinline__ void cpa_wait() {
    asm volatile("cp.async.wait_group %0;" :: "n"(N) : "memory");
}
#define LDSM4(r, a) \
    asm volatile("ldmatrix.sync.aligned.m8n8.x4.shared.b16 {%0,%1,%2,%3}, [%4];" \
                 : "=r"((r)[0]), "=r"((r)[1]), "=r"((r)[2]), "=r"((r)[3]) : "r"(a))
#define MMA16816(d, a, b0, b1) \
    asm volatile("mma.sync.aligned.m16n8k16.row.col.f32.f16.f16.f32 " \
                 "{%0,%1,%2,%3},{%4,%5,%6,%7},{%8,%9},{%0,%1,%2,%3};" \
                 : "+f"((d)[0]), "+f"((d)[1]), "+f"((d)[2]), "+f"((d)[3]) \
                 : "r"((a)[0]), "r"((a)[1]), "r"((a)[2]), "r"((a)[3]), "r"(b0), "r"(b1))

// ---------------- GEMM config: 128x64 CTA tile, 2 CTAs/SM ----------------
#define BM 128
#define BN 64
#define BK 64                       // fp16 elems per chunk (128 B per row)
#define NCH (KK / BK)               // 8
#define NSTG 3
#define TILEA (BM * 128)            // 16384 B
#define TILEB (BN * 128)            // 8192 B
#define STGB (TILEA + TILEB)        // 24576 B per stage
#define GEMM_SMEM (NSTG * STGB)     // 73728 B

// stage one K-chunk of A and B tiles into smem buffer `buf` (swizzled)
__device__ __forceinline__ void stage_tiles(uint32_t sb, const __half* Ab,
                                            const __half* Bb, int tid,
                                            int chunk, int buf) {
    const uint32_t ab = sb + buf * STGB;
    const uint32_t bbse = ab + TILEA;
    const __half* Ap = Ab + chunk * BK;
    const __half* Bp = Bb + chunk * BK;
#pragma unroll
    for (int i = 0; i < 4; i++) {
        int line = tid + i * 256;            // 0..1023
        int row = line >> 3, j = line & 7;   // 16B granule
        uint32_t sw = row * 128 + ((j ^ (row & 7)) << 4);
        cpa16(ab + sw, Ap + (size_t)row * KK + j * 8);
    }
#pragma unroll
    for (int i = 0; i < 2; i++) {
        int line = tid + i * 256;            // 0..511
        int row = line >> 3, j = line & 7;
        uint32_t sw = row * 128 + ((j ^ (row & 7)) << 4);
        cpa16(bbse + sw, Bp + (size_t)row * KK + j * 8);
    }
    cpa_commit();
}

// C[M,Nn] = A'[M,512]h @ B'[Nn,512]h^T + bias (fp32 accum)
__global__ __launch_bounds__(256, 2)
void gemm_half(const __half* __restrict__ A, const __half* __restrict__ Bm,
               const float* __restrict__ bias, float* __restrict__ C, int Nn) {
    extern __shared__ char smem[];
    const uint32_t sb = smem_u32(smem);
    const int tid = threadIdx.x;
    const int wid = tid >> 5;
    const int lane = tid & 31;
    const int bm = blockIdx.y * BM;
    const int bn = blockIdx.x * BN;
    const int wm0 = (wid & 3) * 32;          // warp M offset (4 warps in M)
    const int wn0 = (wid >> 2) * 32;         // warp N offset (2 warps in N)

    const __half* Ab = A + (size_t)bm * KK;
    const __half* Bb = Bm + (size_t)bn * KK;

    float acc[2][4][4];
#pragma unroll
    for (int i = 0; i < 2; i++)
#pragma unroll
        for (int j = 0; j < 4; j++)
#pragma unroll
            for (int k = 0; k < 4; k++) acc[i][j][k] = 0.f;

    const int lrA = (lane & 7) + ((lane >> 3) & 1) * 8;   // row in m16 tile
    const int lcA = ((lane >> 4) & 1) * 16;               // 0 / 16 bytes (k half)
    const int lrB = ((lane >> 4) & 1) * 8 + (lane & 7);
    const int lcB = ((lane >> 3) & 1) * 16;

    stage_tiles(sb, Ab, Bb, tid, 0, 0);
    stage_tiles(sb, Ab, Bb, tid, 1, 1);

    for (int c = 0; c < NCH; c++) {
        if (c + 2 < NCH) cpa_wait<1>(); else cpa_wait<0>();
        __syncthreads();
        if (c + 2 < NCH) stage_tiles(sb, Ab, Bb, tid, c + 2, (c + 2) % NSTG);
        const uint32_t ab = sb + (c % NSTG) * STGB;
        const uint32_t bbse = ab + TILEA;
#pragma unroll
        for (int ks = 0; ks < 4; ks++) {
            uint32_t afr[2][4], bfr[2][4];
#pragma unroll
            for (int mi = 0; mi < 2; mi++) {
                int r = wm0 + mi * 16 + lrA;
                uint32_t cc = (uint32_t)(ks * 32 + lcA);
                LDSM4(afr[mi], ab + r * 128 + (cc ^ ((r & 7) << 4)));
            }
#pragma unroll
            for (int bi = 0; bi < 2; bi++) {
                int r = wn0 + bi * 16 + lrB;
                uint32_t cc = (uint32_t)(ks * 32 + lcB);
                LDSM4(bfr[bi], bbse + r * 128 + (cc ^ ((r & 7) << 4)));
            }
#pragma unroll
            for (int mi = 0; mi < 2; mi++)
#pragma unroll
                for (int nj = 0; nj < 4; nj++)
                    MMA16816(acc[mi][nj], afr[mi],
                             bfr[nj >> 1][(nj & 1) * 2], bfr[nj >> 1][(nj & 1) * 2 + 1]);
        }
    }

    // epilogue: direct float2 stores + bias
    const int g = lane >> 2, t4 = lane & 3;
#pragma unroll
    for (int mi = 0; mi < 2; mi++) {
#pragma unroll
        for (int nj = 0; nj < 4; nj++) {
            const int col = bn + wn0 + nj * 8 + t4 * 2;
            const float2 bv = *(const float2*)(bias + col);
            const int row0 = bm + wm0 + mi * 16 + g;
            float2 o0 = {acc[mi][nj][0] + bv.x, acc[mi][nj][1] + bv.y};
            float2 o1 = {acc[mi][nj][2] + bv.x, acc[mi][nj][3] + bv.y};
            *(float2*)(C + (size_t)row0 * Nn + col) = o0;
            *(float2*)(C + (size_t)(row0 + 8) * Nn + col) = o1;
        }
    }
}

// ---------------- fp16 hi/lo split: [R,256]f32 -> [R,512]h ----------------
__global__ void split_half(const float* __restrict__ in, __half* __restrict__ out,
                           int total, int mode) {
    int i = blockIdx.x * 256 + threadIdx.x;
    if (i >= total) return;
    int row = i >> 8, c = i & 255;
    float v = in[i];
    __half hi = __float2half_rn(v);
    __half lo = __float2half_rn(v - __half2float(hi));
    size_t base = (size_t)row * KK + c;
    out[base] = hi;
    out[base + 256] = (mode == 0) ? lo : hi;
}

// ---------------- zero state accumulators ----------------
__global__ void zero_kernel() {
    int i = blockIdx.x * 256 + threadIdx.x;
    if (i < BB * NH * HD * HD) g_kv[i] = 0.f;
    if (i < BB * NH * HD) { g_km[i] = 0.f; g_vm[i] = 0.f; }
}

// ---------------- per-(b,h) state reduction over N ----------------
#define CHUNK 512
__global__ __launch_bounds__(256)
void reduce_kernel(const float* __restrict__ sinp, const float* __restrict__ cosp) {
    const int bh = blockIdx.x;
    const int chunk = blockIdx.y;
    const int b = bh / NH, h = bh % NH;
    const int tid = threadIdx.x;
    const int j = tid >> 5;
    const int d = tid & 31;
    const int e = d;
    const int dbase = j * 4;
    __shared__ float s_ks[8][32];
    __shared__ float s_vs[8][32];
    float acc[4] = {0.f, 0.f, 0.f, 0.f};
    float ksum = 0.f, vsum = 0.f;
    const int n0 = chunk * CHUNK;
    const float sgn = (d & 1) ? 1.f : -1.f;

    for (int nb = 0; nb < CHUNK; nb += 8) {
        const int n = n0 + nb + j;
        const size_t row = ((size_t)b * SEQ + n) * QKVO;
        const float kval  = g_qkvo[row + INTERNAL + h * HD + d];
        const float kpair = g_qkvo[row + INTERNAL + h * HD + (d ^ 1)];
        const float vval  = g_qkvo[row + 2 * INTERNAL + h * HD + d];
        const float kh  = elu1(kval);
        const float khp = elu1(kpair);
        const float sn = sinp[n * HD + d];
        const float cs = cosp[n * HD + d];
        const float ks = kh * cs + sgn * khp * sn;
        __syncthreads();
        s_ks[j][d] = ks * S_CONST;
        s_vs[j][d] = vval * S_CONST;
        ksum += kh;
        vsum += vval;
        __syncthreads();
#pragma unroll
        for (int jj = 0; jj < 8; jj++) {
            const float vv = s_vs[jj][e];
#pragma unroll
            for (int dd = 0; dd < 4; dd++)
                acc[dd] += s_ks[jj][dbase + dd] * vv;
        }
    }
#pragma unroll
    for (int dd = 0; dd < 4; dd++)
        atomicAdd(&g_kv[(bh * HD + dbase + dd) * HD + e], acc[dd]);
    atomicAdd(&g_km[bh * HD + d], ksum);
    atomicAdd(&g_vm[bh * HD + d], vsum);
}

// ---------------- per-token epilogue: kv in registers, 2-token ILP ----------------
#define TB 32
__global__ __launch_bounds__(256)
void attn_kernel(const float* __restrict__ sinp, const float* __restrict__ cosp,
                 const float* __restrict__ W_lepe, const float* __restrict__ b_lepe) {
    const int b = blockIdx.y;
    const int n0 = blockIdx.x * TB;
    const int h = threadIdx.x >> 5;
    const int lane = threadIdx.x & 31;
    __shared__ float s_kv[NH][HD][HD];
    __shared__ float s_km[NH * HD], s_vm[NH * HD];
    for (int i = threadIdx.x; i < NH * HD * HD; i += 256)
        ((float*)s_kv)[i] = g_kv[b * NH * HD * HD + i];
    const float invN = 1.f / (float)SEQ;
    for (int i = threadIdx.x; i < NH * HD; i += 256) {
        s_km[i] = g_km[b * NH * HD + i] * invN;
        s_vm[i] = g_vm[b * NH * HD + i] * invN;
    }
    __syncthreads();

    // hoist this thread's kv column (e = lane) into registers
    float kvreg[HD];
#pragma unroll
    for (int dd = 0; dd < HD; dd++) kvreg[dd] = s_kv[h][dd][lane];

    const float km = s_km[h * HD + lane];
    const float vm = s_vm[h * HD + lane];
    const float sgn = (lane & 1) ? 1.f : -1.f;
    const int c = h * HD + lane;
    const float w0 = W_lepe[c * 3 + 0];
    const float w1 = W_lepe[c * 3 + 1];
    const float w2 = W_lepe[c * 3 + 2];
    const float bl = b_lepe[c];
    const unsigned FM = 0xffffffffu;

    for (int t = 0; t < TB; t += 2) {
        const int n = n0 + t;
        const size_t row0 = ((size_t)b * SEQ + n) * QKVO;
        const size_t row1 = row0 + QKVO;
        const float qh0 = elu1(g_qkvo[row0 + c]);
        const float qh1 = elu1(g_qkvo[row1 + c]);
        float zv0 = qh0 * km, zv1 = qh1 * km;
#pragma unroll
        for (int off = 16; off; off >>= 1) {
            zv0 += __shfl_xor_sync(FM, zv0, off);
            zv1 += __shfl_xor_sync(FM, zv1, off);
        }
        const float z0 = zv0 * SCALE_F, z1 = zv1 * SCALE_F;
        const float qhp0 = __shfl_xor_sync(FM, qh0, 1);
        const float qhp1 = __shfl_xor_sync(FM, qh1, 1);
        const float sn0 = sinp[n * HD + lane], cs0 = cosp[n * HD + lane];
        const float sn1 = sinp[(n + 1) * HD + lane], cs1 = cosp[(n + 1) * HD + lane];
        const float qs0 = qh0 * cs0 + sgn * qhp0 * sn0;
        const float qs1 = qh1 * cs1 + sgn * qhp1 * sn1;

        float a00 = 0.f, a01 = 0.f, a02 = 0.f, a03 = 0.f;
        float a10 = 0.f, a11 = 0.f, a12 = 0.f, a13 = 0.f;
#pragma unroll
        for (int dd = 0; dd < HD; dd += 4) {
            const float p00 = __shfl_sync(FM, qs0, dd);
            const float p01 = __shfl_sync(FM, qs0, dd + 1);
            const float p02 = __shfl_sync(FM, qs0, dd + 2);
            const float p03 = __shfl_sync(FM, qs0, dd + 3);
            const float p10 = __shfl_sync(FM, qs1, dd);
            const float p11 = __shfl_sync(FM, qs1, dd + 1);
            const float p12 = __shfl_sync(FM, qs1, dd + 2);
            const float p13 = __shfl_sync(FM, qs1, dd + 3);
            a00 += p00 * kvreg[dd];     a01 += p01 * kvreg[dd + 1];
            a02 += p02 * kvreg[dd + 2]; a03 += p03 * kvreg[dd + 3];
            a10 += p10 * kvreg[dd];     a11 += p11 * kvreg[dd + 1];
            a12 += p12 * kvreg[dd + 2]; a13 += p13 * kvreg[dd + 3];
        }
        const float acc0 = (a00 + a01) + (a02 + a03);
        const float acc1 = (a10 + a11) + (a12 + a13);
        const float res0 = acc0 * (1.f + 1.f / (z0 + 1e-6f)) - z0 * vm;
        const float res1 = acc1 * (1.f + 1.f / (z1 + 1e-6f)) - z1 * vm;

        // lepe: v[n-1], v[n], v[n+1], v[n+2] (shared across the token pair)
        const float vprev = (n > 0) ? g_qkvo[row0 - QKVO + 2 * INTERNAL + c] : 0.f;
        const float v0 = g_qkvo[row0 + 2 * INTERNAL + c];
        const float v1 = g_qkvo[row1 + 2 * INTERNAL + c];
        const float vnext = (n + 2 < SEQ) ? g_qkvo[row1 + QKVO + 2 * INTERNAL + c] : 0.f;
        const float lepe0 = vprev * w0 + v0 * w1 + v1 * w2 + bl;
        const float lepe1 = v0 * w0 + v1 * w1 + vnext * w2 + bl;
        const float og0 = g_qkvo[row0 + 3 * INTERNAL + c];
        const float og1 = g_qkvo[row1 + 3 * INTERNAL + c];
        const float r0 = (res0 + lepe0) * og0;
        const float r1 = (res1 + lepe1) * og1;

        __half hi0 = __float2half_rn(r0);
        __half lo0 = __float2half_rn(r0 - __half2float(hi0));
        __half hi1 = __float2half_rn(r1);
        __half lo1 = __float2half_rn(r1 - __half2float(hi1));
        const size_t ob0 = ((size_t)b * SEQ + n) * KK + c;
        g_tmph[ob0] = hi0;
        g_tmph[ob0 + 256] = lo0;
        g_tmph[ob0 + KK] = hi1;
        g_tmph[ob0 + KK + 256] = lo1;
    }
}

// ---------------- launch ----------------
extern "C" void kernel_launch(void* const* d_in, const int* in_sizes, int n_in,
                              void* d_out, int out_size) {
    const float* x      = (const float*)d_in[0];
    const float* sinp   = (const float*)d_in[1];
    const float* cosp   = (const float*)d_in[2];
    const float* W_qkvo = (const float*)d_in[3];
    const float* b_qkvo = (const float*)d_in[4];
    const float* W_lepe = (const float*)d_in[5];
    const float* b_lepe = (const float*)d_in[6];
    const float* W_proj = (const float*)d_in[7];
    const float* b_proj = (const float*)d_in[8];
    float* out = (float*)d_out;

    __half *xs_p, *ws_p, *tmph_p, *wp_p;
    float* qkvo_p;
    cudaGetSymbolAddress((void**)&qkvo_p, g_qkvo);
    cudaGetSymbolAddress((void**)&xs_p, g_xs);
    cudaGetSymbolAddress((void**)&ws_p, g_ws);
    cudaGetSymbolAddress((void**)&tmph_p, g_tmph);
    cudaGetSymbolAddress((void**)&wp_p, g_wp);

    cudaFuncSetAttribute(gemm_half, cudaFuncAttributeMaxDynamicSharedMemorySize, GEMM_SMEM);

    const int M = BB * SEQ;  // 32768

    // 0) fp16 hi/lo splits
    split_half<<<(M * DIM + 255) / 256, 256>>>(x, xs_p, M * DIM, 0);
    split_half<<<(QKVO * DIM + 255) / 256, 256>>>(W_qkvo, ws_p, QKVO * DIM, 1);
    split_half<<<(DIM * DIM + 255) / 256, 256>>>(W_proj, wp_p, DIM * DIM, 1);

    // 1) qkvo = x @ W_qkvo^T + b  (HMMA, K=512 split)
    {
        dim3 grid(QKVO / BN, M / BM);
        gemm_half<<<grid, 256, GEMM_SMEM>>>(xs_p, ws_p, b_qkvo, qkvo_p, QKVO);
    }
    // 2) zero accumulators
    zero_kernel<<<(BB * NH * HD * HD + 255) / 256, 256>>>();
    // 3) state reduction
    {
        dim3 grid(BB * NH, SEQ / CHUNK);
        reduce_kernel<<<grid, 256>>>(sinp, cosp);
    }
    // 4) attention epilogue (writes fp16 hi/lo)
    {
        dim3 grid(SEQ / TB, BB);
        attn_kernel<<<grid, 256>>>(sinp, cosp, W_lepe, b_lepe);
    }
    // 5) out = tmp @ W_proj^T + b_proj  (HMMA)
    {
        dim3 grid(DIM / BN, M / BM);
        gemm_half<<<grid, 256, GEMM_SMEM>>>(tmph_p, wp_p, b_proj, out, DIM);
    }
}

// round 5
// speedup vs baseline: 2.0808x; 1.0003x over previous
#include <cuda_runtime.h>
#include <cuda_fp16.h>
#include <math.h>
#include <stdint.h>

#define BB 4
#define SEQ 8192
#define DIM 256
#define NH 8
#define HD 32
#define INTERNAL 256
#define QKVO 1024
#define KK 512                      // split K (2 x 256)
#define SCALE_F 0.17677669529663687f
#define S_CONST 0.00464534038f

// ---------------- scratch ----------------
__device__ __align__(16) float g_qkvo[(size_t)BB * SEQ * QKVO];      // 128 MB
__device__ __align__(16) __half g_xs[(size_t)BB * SEQ * KK];         // 32 MB
__device__ __align__(16) __half g_ws[(size_t)QKVO * KK];             // 1 MB
__device__ __align__(16) __half g_tmph[(size_t)BB * SEQ * KK];       // 32 MB
__device__ __align__(16) __half g_wp[(size_t)DIM * KK];              // 256 KB
__device__ float g_kv[BB * NH * HD * HD];
__device__ float g_km[BB * NH * HD];
__device__ float g_vm[BB * NH * HD];

__device__ __forceinline__ float elu1(float x) { return x > 0.f ? x + 1.f : expf(x); }

__device__ __forceinline__ uint32_t smem_u32(const void* p) {
    return (uint32_t)__cvta_generic_to_shared(p);
}
__device__ __forceinline__ void cpa16(uint32_t dst, const void* src) {
    asm volatile("cp.async.cg.shared.global [%0], [%1], 16;" :: "r"(dst), "l"(src));
}
__device__ __forceinline__ void cpa_commit() {
    asm volatile("cp.async.commit_group;" ::: "memory");
}
template <int N> __device__ __forceinline__ void cpa_wait() {
    asm volatile("cp.async.wait_group %0;" :: "n"(N) : "memory");
}
#define LDSM4(r, a) \
    asm volatile("ldmatrix.sync.aligned.m8n8.x4.shared.b16 {%0,%1,%2,%3}, [%4];" \
                 : "=r"((r)[0]), "=r"((r)[1]), "=r"((r)[2]), "=r"((r)[3]) : "r"(a))
#define MMA16816(d, a, b0, b1) \
    asm volatile("mma.sync.aligned.m16n8k16.row.col.f32.f16.f16.f32 " \
                 "{%0,%1,%2,%3},{%4,%5,%6,%7},{%8,%9},{%0,%1,%2,%3};" \
                 : "+f"((d)[0]), "+f"((d)[1]), "+f"((d)[2]), "+f"((d)[3]) \
                 : "r"((a)[0]), "r"((a)[1]), "r"((a)[2]), "r"((a)[3]), "r"(b0), "r"(b1))

// ---------------- GEMM config: 128x64 CTA tile, 2 CTAs/SM ----------------
#define BM 128
#define BN 64
#define BK 64
#define NCH (KK / BK)               // 8
#define NSTG 3
#define TILEA (BM * 128)
#define TILEB (BN * 128)
#define STGB (TILEA + TILEB)
#define GEMM_SMEM (NSTG * STGB)     // 73728 B

__device__ __forceinline__ void stage_tiles(uint32_t sb, const __half* Ab,
                                            const __half* Bb, int tid,
                                            int chunk, int buf) {
    const uint32_t ab = sb + buf * STGB;
    const uint32_t bbse = ab + TILEA;
    const __half* Ap = Ab + chunk * BK;
    const __half* Bp = Bb + chunk * BK;
#pragma unroll
    for (int i = 0; i < 4; i++) {
        int line = tid + i * 256;
        int row = line >> 3, j = line & 7;
        uint32_t sw = row * 128 + ((j ^ (row & 7)) << 4);
        cpa16(ab + sw, Ap + (size_t)row * KK + j * 8);
    }
#pragma unroll
    for (int i = 0; i < 2; i++) {
        int line = tid + i * 256;
        int row = line >> 3, j = line & 7;
        uint32_t sw = row * 128 + ((j ^ (row & 7)) << 4);
        cpa16(bbse + sw, Bp + (size_t)row * KK + j * 8);
    }
    cpa_commit();
}

__global__ __launch_bounds__(256, 2)
void gemm_half(const __half* __restrict__ A, const __half* __restrict__ Bm,
               const float* __restrict__ bias, float* __restrict__ C, int Nn) {
    extern __shared__ char smem[];
    const uint32_t sb = smem_u32(smem);
    const int tid = threadIdx.x;
    const int wid = tid >> 5;
    const int lane = tid & 31;
    const int bm = blockIdx.y * BM;
    const int bn = blockIdx.x * BN;
    const int wm0 = (wid & 3) * 32;
    const int wn0 = (wid >> 2) * 32;

    const __half* Ab = A + (size_t)bm * KK;
    const __half* Bb = Bm + (size_t)bn * KK;

    float acc[2][4][4];
#pragma unroll
    for (int i = 0; i < 2; i++)
#pragma unroll
        for (int j = 0; j < 4; j++)
#pragma unroll
            for (int k = 0; k < 4; k++) acc[i][j][k] = 0.f;

    const int lrA = (lane & 7) + ((lane >> 3) & 1) * 8;
    const int lcA = ((lane >> 4) & 1) * 16;
    const int lrB = ((lane >> 4) & 1) * 8 + (lane & 7);
    const int lcB = ((lane >> 3) & 1) * 16;

    stage_tiles(sb, Ab, Bb, tid, 0, 0);
    stage_tiles(sb, Ab, Bb, tid, 1, 1);

    for (int c = 0; c < NCH; c++) {
        if (c + 2 < NCH) cpa_wait<1>(); else cpa_wait<0>();
        __syncthreads();
        if (c + 2 < NCH) stage_tiles(sb, Ab, Bb, tid, c + 2, (c + 2) % NSTG);
        const uint32_t ab = sb + (c % NSTG) * STGB;
        const uint32_t bbse = ab + TILEA;
#pragma unroll
        for (int ks = 0; ks < 4; ks++) {
            uint32_t afr[2][4], bfr[2][4];
#pragma unroll
            for (int mi = 0; mi < 2; mi++) {
                int r = wm0 + mi * 16 + lrA;
                uint32_t cc = (uint32_t)(ks * 32 + lcA);
                LDSM4(afr[mi], ab + r * 128 + (cc ^ ((r & 7) << 4)));
            }
#pragma unroll
            for (int bi = 0; bi < 2; bi++) {
                int r = wn0 + bi * 16 + lrB;
                uint32_t cc = (uint32_t)(ks * 32 + lcB);
                LDSM4(bfr[bi], bbse + r * 128 + (cc ^ ((r & 7) << 4)));
            }
#pragma unroll
            for (int mi = 0; mi < 2; mi++)
#pragma unroll
                for (int nj = 0; nj < 4; nj++)
                    MMA16816(acc[mi][nj], afr[mi],
                             bfr[nj >> 1][(nj & 1) * 2], bfr[nj >> 1][(nj & 1) * 2 + 1]);
        }
    }

    const int g = lane >> 2, t4 = lane & 3;
#pragma unroll
    for (int mi = 0; mi < 2; mi++) {
#pragma unroll
        for (int nj = 0; nj < 4; nj++) {
            const int col = bn + wn0 + nj * 8 + t4 * 2;
            const float2 bv = *(const float2*)(bias + col);
            const int row0 = bm + wm0 + mi * 16 + g;
            float2 o0 = {acc[mi][nj][0] + bv.x, acc[mi][nj][1] + bv.y};
            float2 o1 = {acc[mi][nj][2] + bv.x, acc[mi][nj][3] + bv.y};
            *(float2*)(C + (size_t)row0 * Nn + col) = o0;
            *(float2*)(C + (size_t)(row0 + 8) * Nn + col) = o1;
        }
    }
}

// ---------------- fp16 hi/lo split ----------------
__global__ void split_half(const float* __restrict__ in, __half* __restrict__ out,
                           int total, int mode) {
    int i = blockIdx.x * 256 + threadIdx.x;
    if (i >= total) return;
    int row = i >> 8, c = i & 255;
    float v = in[i];
    __half hi = __float2half_rn(v);
    __half lo = __float2half_rn(v - __half2float(hi));
    size_t base = (size_t)row * KK + c;
    out[base] = hi;
    out[base + 256] = (mode == 0) ? lo : hi;
}

// ---------------- zero state accumulators ----------------
__global__ void zero_kernel() {
    int i = blockIdx.x * 256 + threadIdx.x;
    if (i < BB * NH * HD * HD) g_kv[i] = 0.f;
    if (i < BB * NH * HD) { g_km[i] = 0.f; g_vm[i] = 0.f; }
}

// ---------------- per-(b,h) state reduction over N ----------------
#define CHUNK 512
__global__ __launch_bounds__(256)
void reduce_kernel(const float* __restrict__ sinp, const float* __restrict__ cosp) {
    const int bh = blockIdx.x;
    const int chunk = blockIdx.y;
    const int b = bh / NH, h = bh % NH;
    const int tid = threadIdx.x;
    const int j = tid >> 5;
    const int d = tid & 31;
    const int e = d;
    const int dbase = j * 4;
    __shared__ float s_ks[8][32];
    __shared__ float s_vs[8][32];
    float acc[4] = {0.f, 0.f, 0.f, 0.f};
    float ksum = 0.f, vsum = 0.f;
    const int n0 = chunk * CHUNK;
    const float sgn = (d & 1) ? 1.f : -1.f;

    for (int nb = 0; nb < CHUNK; nb += 8) {
        const int n = n0 + nb + j;
        const size_t row = ((size_t)b * SEQ + n) * QKVO;
        const float kval  = g_qkvo[row + INTERNAL + h * HD + d];
        const float kpair = g_qkvo[row + INTERNAL + h * HD + (d ^ 1)];
        const float vval  = g_qkvo[row + 2 * INTERNAL + h * HD + d];
        const float kh  = elu1(kval);
        const float khp = elu1(kpair);
        const float sn = sinp[n * HD + d];
        const float cs = cosp[n * HD + d];
        const float ks = kh * cs + sgn * khp * sn;
        __syncthreads();
        s_ks[j][d] = ks * S_CONST;
        s_vs[j][d] = vval * S_CONST;
        ksum += kh;
        vsum += vval;
        __syncthreads();
#pragma unroll
        for (int jj = 0; jj < 8; jj++) {
            const float vv = s_vs[jj][e];
#pragma unroll
            for (int dd = 0; dd < 4; dd++)
                acc[dd] += s_ks[jj][dbase + dd] * vv;
        }
    }
#pragma unroll
    for (int dd = 0; dd < 4; dd++)
        atomicAdd(&g_kv[(bh * HD + dbase + dd) * HD + e], acc[dd]);
    atomicAdd(&g_km[bh * HD + d], ksum);
    atomicAdd(&g_vm[bh * HD + d], vsum);
}

// ---------------- attn epilogue: thread-per-(token,head), zero shuffles ----------------
#define ATB 256
__global__ __launch_bounds__(256)
void attn_kernel(const float* __restrict__ sinp, const float* __restrict__ cosp,
                 const float* __restrict__ W_lepe, const float* __restrict__ b_lepe) {
    const int b = blockIdx.y;
    const int h = blockIdx.z;
    const int n = blockIdx.x * ATB + threadIdx.x;
    const int bh = b * NH + h;
    __shared__ __align__(16) float s_kv[HD][HD];
    __shared__ float s_km[HD], s_vm[HD], s_w0[HD], s_w1[HD], s_w2[HD], s_bl[HD];

    for (int i = threadIdx.x; i < HD * HD; i += 256)
        ((float*)s_kv)[i] = g_kv[bh * HD * HD + i];
    if (threadIdx.x < HD) {
        const int c = h * HD + threadIdx.x;
        const float invN = 1.f / (float)SEQ;
        s_km[threadIdx.x] = g_km[bh * HD + threadIdx.x] * invN;
        s_vm[threadIdx.x] = g_vm[bh * HD + threadIdx.x] * invN;
        s_w0[threadIdx.x] = W_lepe[c * 3 + 0];
        s_w1[threadIdx.x] = W_lepe[c * 3 + 1];
        s_w2[threadIdx.x] = W_lepe[c * 3 + 2];
        s_bl[threadIdx.x] = b_lepe[c];
    }
    __syncthreads();

    const size_t row = ((size_t)b * SEQ + n) * QKVO;
    const int cb = h * HD;

    // q row -> registers, elu+1
    float qh[HD];
#pragma unroll
    for (int d4 = 0; d4 < 8; d4++) {
        float4 v = *(const float4*)(g_qkvo + row + cb + d4 * 4);
        qh[d4 * 4 + 0] = elu1(v.x);
        qh[d4 * 4 + 1] = elu1(v.y);
        qh[d4 * 4 + 2] = elu1(v.z);
        qh[d4 * 4 + 3] = elu1(v.w);
    }
    // z = SCALE * dot(qh, kmean)
    float z = 0.f;
#pragma unroll
    for (int d = 0; d < HD; d++) z += qh[d] * s_km[d];
    z *= SCALE_F;

    // theta shift in place (rotate_every_two)
#pragma unroll
    for (int d4 = 0; d4 < 8; d4++) {
        float4 sn = *(const float4*)(sinp + (size_t)n * HD + d4 * 4);
        float4 cs = *(const float4*)(cosp + (size_t)n * HD + d4 * 4);
        const float a0 = qh[d4 * 4 + 0], a1 = qh[d4 * 4 + 1];
        const float a2 = qh[d4 * 4 + 2], a3 = qh[d4 * 4 + 3];
        qh[d4 * 4 + 0] = a0 * cs.x - a1 * sn.x;
        qh[d4 * 4 + 1] = a1 * cs.y + a0 * sn.y;
        qh[d4 * 4 + 2] = a2 * cs.z - a3 * sn.z;
        qh[d4 * 4 + 3] = a3 * cs.w + a2 * sn.w;
    }

    // acc[e] = sum_d qs[d] * kv[d][e]  (broadcast LDS.128)
    float acc[HD];
#pragma unroll
    for (int e = 0; e < HD; e++) acc[e] = 0.f;
#pragma unroll
    for (int d = 0; d < HD; d++) {
        const float qd = qh[d];
        const float4* kvr = (const float4*)s_kv[d];
#pragma unroll
        for (int e4 = 0; e4 < 8; e4++) {
            float4 kv4 = kvr[e4];
            acc[e4 * 4 + 0] += qd * kv4.x;
            acc[e4 * 4 + 1] += qd * kv4.y;
            acc[e4 * 4 + 2] += qd * kv4.z;
            acc[e4 * 4 + 3] += qd * kv4.w;
        }
    }

    const float zf = 1.f + 1.f / (z + 1e-6f);
    const bool hp = (n > 0), hn = (n < SEQ - 1);
    const float* vrow = g_qkvo + row + 2 * INTERNAL + cb;
    const float* orow = g_qkvo + row + 3 * INTERNAL + cb;
    __half* outp = g_tmph + ((size_t)b * SEQ + n) * KK + cb;

#pragma unroll
    for (int e4 = 0; e4 < 8; e4++) {
        const float4 v0 = *(const float4*)(vrow + e4 * 4);
        const float4 vp = hp ? *(const float4*)(vrow - QKVO + e4 * 4) : make_float4(0, 0, 0, 0);
        const float4 vn = hn ? *(const float4*)(vrow + QKVO + e4 * 4) : make_float4(0, 0, 0, 0);
        const float4 og = *(const float4*)(orow + e4 * 4);
        const int e = e4 * 4;
        float r0 = (acc[e + 0] * zf - z * s_vm[e + 0]
                    + vp.x * s_w0[e + 0] + v0.x * s_w1[e + 0] + vn.x * s_w2[e + 0] + s_bl[e + 0]) * og.x;
        float r1 = (acc[e + 1] * zf - z * s_vm[e + 1]
                    + vp.y * s_w0[e + 1] + v0.y * s_w1[e + 1] + vn.y * s_w2[e + 1] + s_bl[e + 1]) * og.y;
        float r2 = (acc[e + 2] * zf - z * s_vm[e + 2]
                    + vp.z * s_w0[e + 2] + v0.z * s_w1[e + 2] + vn.z * s_w2[e + 2] + s_bl[e + 2]) * og.z;
        float r3 = (acc[e + 3] * zf - z * s_vm[e + 3]
                    + vp.w * s_w0[e + 3] + v0.w * s_w1[e + 3] + vn.w * s_w2[e + 3] + s_bl[e + 3]) * og.w;
        __half h0 = __float2half_rn(r0), h1 = __float2half_rn(r1);
        __half h2 = __float2half_rn(r2), h3 = __float2half_rn(r3);
        __half l0 = __float2half_rn(r0 - __half2float(h0));
        __half l1 = __float2half_rn(r1 - __half2float(h1));
        __half l2 = __float2half_rn(r2 - __half2float(h2));
        __half l3 = __float2half_rn(r3 - __half2float(h3));
        uint2 hw, lw;
        hw.x = ((uint32_t)__half_as_ushort(h1) << 16) | __half_as_ushort(h0);
        hw.y = ((uint32_t)__half_as_ushort(h3) << 16) | __half_as_ushort(h2);
        lw.x = ((uint32_t)__half_as_ushort(l1) << 16) | __half_as_ushort(l0);
        lw.y = ((uint32_t)__half_as_ushort(l3) << 16) | __half_as_ushort(l2);
        *(uint2*)(outp + e) = hw;
        *(uint2*)(outp + 256 + e) = lw;
    }
}

// ---------------- launch ----------------
extern "C" void kernel_launch(void* const* d_in, const int* in_sizes, int n_in,
                              void* d_out, int out_size) {
    const float* x      = (const float*)d_in[0];
    const float* sinp   = (const float*)d_in[1];
    const float* cosp   = (const float*)d_in[2];
    const float* W_qkvo = (const float*)d_in[3];
    const float* b_qkvo = (const float*)d_in[4];
    const float* W_lepe = (const float*)d_in[5];
    const float* b_lepe = (const float*)d_in[6];
    const float* W_proj = (const float*)d_in[7];
    const float* b_proj = (const float*)d_in[8];
    float* out = (float*)d_out;

    __half *xs_p, *ws_p, *tmph_p, *wp_p;
    float* qkvo_p;
    cudaGetSymbolAddress((void**)&qkvo_p, g_qkvo);
    cudaGetSymbolAddress((void**)&xs_p, g_xs);
    cudaGetSymbolAddress((void**)&ws_p, g_ws);
    cudaGetSymbolAddress((void**)&tmph_p, g_tmph);
    cudaGetSymbolAddress((void**)&wp_p, g_wp);

    cudaFuncSetAttribute(gemm_half, cudaFuncAttributeMaxDynamicSharedMemorySize, GEMM_SMEM);

    const int M = BB * SEQ;  // 32768

    split_half<<<(M * DIM + 255) / 256, 256>>>(x, xs_p, M * DIM, 0);
    split_half<<<(QKVO * DIM + 255) / 256, 256>>>(W_qkvo, ws_p, QKVO * DIM, 1);
    split_half<<<(DIM * DIM + 255) / 256, 256>>>(W_proj, wp_p, DIM * DIM, 1);

    {
        dim3 grid(QKVO / BN, M / BM);
        gemm_half<<<grid, 256, GEMM_SMEM>>>(xs_p, ws_p, b_qkvo, qkvo_p, QKVO);
    }
    zero_kernel<<<(BB * NH * HD * HD + 255) / 256, 256>>>();
    {
        dim3 grid(BB * NH, SEQ / CHUNK);
        reduce_kernel<<<grid, 256>>>(sinp, cosp);
    }
    {
        dim3 grid(SEQ / ATB, BB, NH);
        attn_kernel<<<grid, 256>>>(sinp, cosp, W_lepe, b_lepe);
    }
    {
        dim3 grid(DIM / BN, M / BM);
        gemm_half<<<grid, 256, GEMM_SMEM>>>(tmph_p, wp_p, b_proj, out, DIM);
    }
}

// round 6
// speedup vs baseline: 2.1678x; 1.0418x over previous
#include <cuda_runtime.h>
#include <cuda_fp16.h>
#include <math.h>
#include <stdint.h>

#define BB 4
#define SEQ 8192
#define DIM 256
#define NH 8
#define HD 32
#define INTERNAL 256
#define QKVO 1024
#define KK 512                      // split K (2 x 256)
#define SCALE_F 0.17677669529663687f
#define S_CONST 0.00464534038f

// ---------------- scratch ----------------
__device__ __align__(16) float g_qkvo[(size_t)BB * SEQ * QKVO];      // 128 MB
__device__ __align__(16) __half g_xs[(size_t)BB * SEQ * KK];         // 32 MB
__device__ __align__(16) __half g_ws[(size_t)QKVO * KK];             // 1 MB
__device__ __align__(16) __half g_tmph[(size_t)BB * SEQ * KK];       // 32 MB
__device__ __align__(16) __half g_wp[(size_t)DIM * KK];              // 256 KB
__device__ float g_kv[BB * NH * HD * HD];
__device__ float g_km[BB * NH * HD];
__device__ float g_vm[BB * NH * HD];

__device__ __forceinline__ float elu1(float x) { return x > 0.f ? x + 1.f : expf(x); }

__device__ __forceinline__ uint32_t smem_u32(const void* p) {
    return (uint32_t)__cvta_generic_to_shared(p);
}
__device__ __forceinline__ void cpa16(uint32_t dst, const void* src) {
    asm volatile("cp.async.cg.shared.global [%0], [%1], 16;" :: "r"(dst), "l"(src));
}
__device__ __forceinline__ void cpa_commit() {
    asm volatile("cp.async.commit_group;" ::: "memory");
}
template <int N> __device__ __forceinline__ void cpa_wait() {
    asm volatile("cp.async.wait_group %0;" :: "n"(N) : "memory");
}
#define LDSM4(r, a) \
    asm volatile("ldmatrix.sync.aligned.m8n8.x4.shared.b16 {%0,%1,%2,%3}, [%4];" \
                 : "=r"((r)[0]), "=r"((r)[1]), "=r"((r)[2]), "=r"((r)[3]) : "r"(a))
#define MMA16816(d, a, b0, b1) \
    asm volatile("mma.sync.aligned.m16n8k16.row.col.f32.f16.f16.f32 " \
                 "{%0,%1,%2,%3},{%4,%5,%6,%7},{%8,%9},{%0,%1,%2,%3};" \
                 : "+f"((d)[0]), "+f"((d)[1]), "+f"((d)[2]), "+f"((d)[3]) \
                 : "r"((a)[0]), "r"((a)[1]), "r"((a)[2]), "r"((a)[3]), "r"(b0), "r"(b1))

// ---------------- GEMM config: 128x128 CTA, warp tile 32x64, 2 CTAs/SM ----------------
#define BM 128
#define BN 128
#define BK 64
#define NCH (KK / BK)               // 8
#define NSTG 3
#define TILEA (BM * 128)            // 16384 B
#define TILEB (BN * 128)            // 16384 B
#define STGB (TILEA + TILEB)        // 32768 B
#define GEMM_SMEM (NSTG * STGB)     // 98304 B

__device__ __forceinline__ void stage_tiles(uint32_t sb, const __half* Ab,
                                            const __half* Bb, int tid,
                                            int chunk, int buf) {
    const uint32_t ab = sb + buf * STGB;
    const uint32_t bbse = ab + TILEA;
    const __half* Ap = Ab + chunk * BK;
    const __half* Bp = Bb + chunk * BK;
#pragma unroll
    for (int i = 0; i < 4; i++) {
        int line = tid + i * 256;            // 0..1023
        int row = line >> 3, j = line & 7;
        uint32_t sw = row * 128 + ((j ^ (row & 7)) << 4);
        cpa16(ab + sw, Ap + (size_t)row * KK + j * 8);
    }
#pragma unroll
    for (int i = 0; i < 4; i++) {
        int line = tid + i * 256;
        int row = line >> 3, j = line & 7;
        uint32_t sw = row * 128 + ((j ^ (row & 7)) << 4);
        cpa16(bbse + sw, Bp + (size_t)row * KK + j * 8);
    }
    cpa_commit();
}

// C[M,Nn] = A'[M,512]h @ B'[Nn,512]h^T + bias (fp32 accum)
__global__ __launch_bounds__(256, 2)
void gemm_half(const __half* __restrict__ A, const __half* __restrict__ Bm,
               const float* __restrict__ bias, float* __restrict__ C, int Nn) {
    extern __shared__ char smem[];
    const uint32_t sb = smem_u32(smem);
    const int tid = threadIdx.x;
    const int wid = tid >> 5;
    const int lane = tid & 31;
    const int bm = blockIdx.y * BM;
    const int bn = blockIdx.x * BN;
    const int wm0 = (wid & 3) * 32;          // 4 warps in M
    const int wn0 = (wid >> 2) * 64;         // 2 warps in N

    const __half* Ab = A + (size_t)bm * KK;
    const __half* Bb = Bm + (size_t)bn * KK;

    float acc[2][8][4];
#pragma unroll
    for (int i = 0; i < 2; i++)
#pragma unroll
        for (int j = 0; j < 8; j++)
#pragma unroll
            for (int k = 0; k < 4; k++) acc[i][j][k] = 0.f;

    const int lrA = (lane & 7) + ((lane >> 3) & 1) * 8;
    const int lcA = ((lane >> 4) & 1) * 16;
    const int lrB = ((lane >> 4) & 1) * 8 + (lane & 7);
    const int lcB = ((lane >> 3) & 1) * 16;

    stage_tiles(sb, Ab, Bb, tid, 0, 0);
    stage_tiles(sb, Ab, Bb, tid, 1, 1);

    for (int c = 0; c < NCH; c++) {
        if (c + 2 < NCH) cpa_wait<1>(); else cpa_wait<0>();
        __syncthreads();
        if (c + 2 < NCH) stage_tiles(sb, Ab, Bb, tid, c + 2, (c + 2) % NSTG);
        const uint32_t ab = sb + (c % NSTG) * STGB;
        const uint32_t bbse = ab + TILEA;
#pragma unroll
        for (int ks = 0; ks < 4; ks++) {
            uint32_t afr[2][4], bfr[4][4];
#pragma unroll
            for (int mi = 0; mi < 2; mi++) {
                int r = wm0 + mi * 16 + lrA;
                uint32_t cc = (uint32_t)(ks * 32 + lcA);
                LDSM4(afr[mi], ab + r * 128 + (cc ^ ((r & 7) << 4)));
            }
#pragma unroll
            for (int bi = 0; bi < 4; bi++) {
                int r = wn0 + bi * 16 + lrB;
                uint32_t cc = (uint32_t)(ks * 32 + lcB);
                LDSM4(bfr[bi], bbse + r * 128 + (cc ^ ((r & 7) << 4)));
            }
#pragma unroll
            for (int mi = 0; mi < 2; mi++)
#pragma unroll
                for (int nj = 0; nj < 8; nj++)
                    MMA16816(acc[mi][nj], afr[mi],
                             bfr[nj >> 1][(nj & 1) * 2], bfr[nj >> 1][(nj & 1) * 2 + 1]);
        }
    }

    const int g = lane >> 2, t4 = lane & 3;
#pragma unroll
    for (int mi = 0; mi < 2; mi++) {
#pragma unroll
        for (int nj = 0; nj < 8; nj++) {
            const int col = bn + wn0 + nj * 8 + t4 * 2;
            const float2 bv = *(const float2*)(bias + col);
            const int row0 = bm + wm0 + mi * 16 + g;
            float2 o0 = {acc[mi][nj][0] + bv.x, acc[mi][nj][1] + bv.y};
            float2 o1 = {acc[mi][nj][2] + bv.x, acc[mi][nj][3] + bv.y};
            *(float2*)(C + (size_t)row0 * Nn + col) = o0;
            *(float2*)(C + (size_t)(row0 + 8) * Nn + col) = o1;
        }
    }
}

// ---------------- fp16 hi/lo split ----------------
__global__ void split_half(const float* __restrict__ in, __half* __restrict__ out,
                           int total, int mode) {
    int i = blockIdx.x * 256 + threadIdx.x;
    if (i >= total) return;
    int row = i >> 8, c = i & 255;
    float v = in[i];
    __half hi = __float2half_rn(v);
    __half lo = __float2half_rn(v - __half2float(hi));
    size_t base = (size_t)row * KK + c;
    out[base] = hi;
    out[base + 256] = (mode == 0) ? lo : hi;
}

// ---------------- zero state accumulators ----------------
__global__ void zero_kernel() {
    int i = blockIdx.x * 256 + threadIdx.x;
    if (i < BB * NH * HD * HD) g_kv[i] = 0.f;
    if (i < BB * NH * HD) { g_km[i] = 0.f; g_vm[i] = 0.f; }
}

// ---------------- per-(b,h) state reduction over N ----------------
#define CHUNK 512
__global__ __launch_bounds__(256)
void reduce_kernel(const float* __restrict__ sinp, const float* __restrict__ cosp) {
    const int bh = blockIdx.x;
    const int chunk = blockIdx.y;
    const int b = bh / NH, h = bh % NH;
    const int tid = threadIdx.x;
    const int j = tid >> 5;
    const int d = tid & 31;
    const int e = d;
    const int dbase = j * 4;
    __shared__ float s_ks[8][32];
    __shared__ float s_vs[8][32];
    float acc[4] = {0.f, 0.f, 0.f, 0.f};
    float ksum = 0.f, vsum = 0.f;
    const int n0 = chunk * CHUNK;
    const float sgn = (d & 1) ? 1.f : -1.f;

    for (int nb = 0; nb < CHUNK; nb += 8) {
        const int n = n0 + nb + j;
        const size_t row = ((size_t)b * SEQ + n) * QKVO;
        const float kval  = g_qkvo[row + INTERNAL + h * HD + d];
        const float kpair = g_qkvo[row + INTERNAL + h * HD + (d ^ 1)];
        const float vval  = g_qkvo[row + 2 * INTERNAL + h * HD + d];
        const float kh  = elu1(kval);
        const float khp = elu1(kpair);
        const float sn = sinp[n * HD + d];
        const float cs = cosp[n * HD + d];
        const float ks = kh * cs + sgn * khp * sn;
        __syncthreads();
        s_ks[j][d] = ks * S_CONST;
        s_vs[j][d] = vval * S_CONST;
        ksum += kh;
        vsum += vval;
        __syncthreads();
#pragma unroll
        for (int jj = 0; jj < 8; jj++) {
            const float vv = s_vs[jj][e];
#pragma unroll
            for (int dd = 0; dd < 4; dd++)
                acc[dd] += s_ks[jj][dbase + dd] * vv;
        }
    }
#pragma unroll
    for (int dd = 0; dd < 4; dd++)
        atomicAdd(&g_kv[(bh * HD + dbase + dd) * HD + e], acc[dd]);
    atomicAdd(&g_km[bh * HD + d], ksum);
    atomicAdd(&g_vm[bh * HD + d], vsum);
}

// ---------------- attn epilogue: thread-per-(token,head), zero shuffles ----------------
#define ATB 256
__global__ __launch_bounds__(256)
void attn_kernel(const float* __restrict__ sinp, const float* __restrict__ cosp,
                 const float* __restrict__ W_lepe, const float* __restrict__ b_lepe) {
    const int b = blockIdx.y;
    const int h = blockIdx.z;
    const int n = blockIdx.x * ATB + threadIdx.x;
    const int bh = b * NH + h;
    __shared__ __align__(16) float s_kv[HD][HD];
    __shared__ float s_km[HD], s_vm[HD], s_w0[HD], s_w1[HD], s_w2[HD], s_bl[HD];

    for (int i = threadIdx.x; i < HD * HD; i += 256)
        ((float*)s_kv)[i] = g_kv[bh * HD * HD + i];
    if (threadIdx.x < HD) {
        const int c = h * HD + threadIdx.x;
        const float invN = 1.f / (float)SEQ;
        s_km[threadIdx.x] = g_km[bh * HD + threadIdx.x] * invN;
        s_vm[threadIdx.x] = g_vm[bh * HD + threadIdx.x] * invN;
        s_w0[threadIdx.x] = W_lepe[c * 3 + 0];
        s_w1[threadIdx.x] = W_lepe[c * 3 + 1];
        s_w2[threadIdx.x] = W_lepe[c * 3 + 2];
        s_bl[threadIdx.x] = b_lepe[c];
    }
    __syncthreads();

    const size_t row = ((size_t)b * SEQ + n) * QKVO;
    const int cb = h * HD;

    float qh[HD];
#pragma unroll
    for (int d4 = 0; d4 < 8; d4++) {
        float4 v = *(const float4*)(g_qkvo + row + cb + d4 * 4);
        qh[d4 * 4 + 0] = elu1(v.x);
        qh[d4 * 4 + 1] = elu1(v.y);
        qh[d4 * 4 + 2] = elu1(v.z);
        qh[d4 * 4 + 3] = elu1(v.w);
    }
    float z = 0.f;
#pragma unroll
    for (int d = 0; d < HD; d++) z += qh[d] * s_km[d];
    z *= SCALE_F;

#pragma unroll
    for (int d4 = 0; d4 < 8; d4++) {
        float4 sn = *(const float4*)(sinp + (size_t)n * HD + d4 * 4);
        float4 cs = *(const float4*)(cosp + (size_t)n * HD + d4 * 4);
        const float a0 = qh[d4 * 4 + 0], a1 = qh[d4 * 4 + 1];
        const float a2 = qh[d4 * 4 + 2], a3 = qh[d4 * 4 + 3];
        qh[d4 * 4 + 0] = a0 * cs.x - a1 * sn.x;
        qh[d4 * 4 + 1] = a1 * cs.y + a0 * sn.y;
        qh[d4 * 4 + 2] = a2 * cs.z - a3 * sn.z;
        qh[d4 * 4 + 3] = a3 * cs.w + a2 * sn.w;
    }

    float acc[HD];
#pragma unroll
    for (int e = 0; e < HD; e++) acc[e] = 0.f;
#pragma unroll
    for (int d = 0; d < HD; d++) {
        const float qd = qh[d];
        const float4* kvr = (const float4*)s_kv[d];
#pragma unroll
        for (int e4 = 0; e4 < 8; e4++) {
            float4 kv4 = kvr[e4];
            acc[e4 * 4 + 0] += qd * kv4.x;
            acc[e4 * 4 + 1] += qd * kv4.y;
            acc[e4 * 4 + 2] += qd * kv4.z;
            acc[e4 * 4 + 3] += qd * kv4.w;
        }
    }

    const float zf = 1.f + 1.f / (z + 1e-6f);
    const bool hp = (n > 0), hn = (n < SEQ - 1);
    const float* vrow = g_qkvo + row + 2 * INTERNAL + cb;
    const float* orow = g_qkvo + row + 3 * INTERNAL + cb;
    __half* outp = g_tmph + ((size_t)b * SEQ + n) * KK + cb;

#pragma unroll
    for (int e4 = 0; e4 < 8; e4++) {
        const float4 v0 = *(const float4*)(vrow + e4 * 4);
        const float4 vp = hp ? *(const float4*)(vrow - QKVO + e4 * 4) : make_float4(0, 0, 0, 0);
        const float4 vn = hn ? *(const float4*)(vrow + QKVO + e4 * 4) : make_float4(0, 0, 0, 0);
        const float4 og = *(const float4*)(orow + e4 * 4);
        const int e = e4 * 4;
        float r0 = (acc[e + 0] * zf - z * s_vm[e + 0]
                    + vp.x * s_w0[e + 0] + v0.x * s_w1[e + 0] + vn.x * s_w2[e + 0] + s_bl[e + 0]) * og.x;
        float r1 = (acc[e + 1] * zf - z * s_vm[e + 1]
                    + vp.y * s_w0[e + 1] + v0.y * s_w1[e + 1] + vn.y * s_w2[e + 1] + s_bl[e + 1]) * og.y;
        float r2 = (acc[e + 2] * zf - z * s_vm[e + 2]
                    + vp.z * s_w0[e + 2] + v0.z * s_w1[e + 2] + vn.z * s_w2[e + 2] + s_bl[e + 2]) * og.z;
        float r3 = (acc[e + 3] * zf - z * s_vm[e + 3]
                    + vp.w * s_w0[e + 3] + v0.w * s_w1[e + 3] + vn.w * s_w2[e + 3] + s_bl[e + 3]) * og.w;
        __half h0 = __float2half_rn(r0), h1 = __float2half_rn(r1);
        __half h2 = __float2half_rn(r2), h3 = __float2half_rn(r3);
        __half l0 = __float2half_rn(r0 - __half2float(h0));
        __half l1 = __float2half_rn(r1 - __half2float(h1));
        __half l2 = __float2half_rn(r2 - __half2float(h2));
        __half l3 = __float2half_rn(r3 - __half2float(h3));
        uint2 hw, lw;
        hw.x = ((uint32_t)__half_as_ushort(h1) << 16) | __half_as_ushort(h0);
        hw.y = ((uint32_t)__half_as_ushort(h3) << 16) | __half_as_ushort(h2);
        lw.x = ((uint32_t)__half_as_ushort(l1) << 16) | __half_as_ushort(l0);
        lw.y = ((uint32_t)__half_as_ushort(l3) << 16) | __half_as_ushort(l2);
        *(uint2*)(outp + e) = hw;
        *(uint2*)(outp + 256 + e) = lw;
    }
}

// ---------------- launch ----------------
extern "C" void kernel_launch(void* const* d_in, const int* in_sizes, int n_in,
                              void* d_out, int out_size) {
    const float* x      = (const float*)d_in[0];
    const float* sinp   = (const float*)d_in[1];
    const float* cosp   = (const float*)d_in[2];
    const float* W_qkvo = (const float*)d_in[3];
    const float* b_qkvo = (const float*)d_in[4];
    const float* W_lepe = (const float*)d_in[5];
    const float* b_lepe = (const float*)d_in[6];
    const float* W_proj = (const float*)d_in[7];
    const float* b_proj = (const float*)d_in[8];
    float* out = (float*)d_out;

    __half *xs_p, *ws_p, *tmph_p, *wp_p;
    float* qkvo_p;
    cudaGetSymbolAddress((void**)&qkvo_p, g_qkvo);
    cudaGetSymbolAddress((void**)&xs_p, g_xs);
    cudaGetSymbolAddress((void**)&ws_p, g_ws);
    cudaGetSymbolAddress((void**)&tmph_p, g_tmph);
    cudaGetSymbolAddress((void**)&wp_p, g_wp);

    cudaFuncSetAttribute(gemm_half, cudaFuncAttributeMaxDynamicSharedMemorySize, GEMM_SMEM);

    const int M = BB * SEQ;  // 32768

    split_half<<<(M * DIM + 255) / 256, 256>>>(x, xs_p, M * DIM, 0);
    split_half<<<(QKVO * DIM + 255) / 256, 256>>>(W_qkvo, ws_p, QKVO * DIM, 1);
    split_half<<<(DIM * DIM + 255) / 256, 256>>>(W_proj, wp_p, DIM * DIM, 1);

    {
        dim3 grid(QKVO / BN, M / BM);
        gemm_half<<<grid, 256, GEMM_SMEM>>>(xs_p, ws_p, b_qkvo, qkvo_p, QKVO);
    }
    zero_kernel<<<(BB * NH * HD * HD + 255) / 256, 256>>>();
    {
        dim3 grid(BB * NH, SEQ / CHUNK);
        reduce_kernel<<<grid, 256>>>(sinp, cosp);
    }
    {
        dim3 grid(SEQ / ATB, BB, NH);
        attn_kernel<<<grid, 256>>>(sinp, cosp, W_lepe, b_lepe);
    }
    {
        dim3 grid(DIM / BN, M / BM);
        gemm_half<<<grid, 256, GEMM_SMEM>>>(tmph_p, wp_p, b_proj, out, DIM);
    }
}

// round 7
// speedup vs baseline: 2.3924x; 1.1036x over previous
#include <cuda_runtime.h>
#include <cuda_fp16.h>
#include <math.h>
#include <stdint.h>

#define BB 4
#define SEQ 8192
#define DIM 256
#define NH 8
#define HD 32
#define INTERNAL 256
#define QKVO 1024
#define KK 512                      // split K (2 x 256)
#define SCALE_F 0.17677669529663687f
#define S_CONST 0.00464534038f

// ---------------- scratch ----------------
__device__ __align__(16) float g_qkvo[(size_t)BB * SEQ * QKVO];      // 128 MB
__device__ __align__(16) __half g_xs[(size_t)BB * SEQ * KK];         // 32 MB
__device__ __align__(16) __half g_ws[(size_t)QKVO * KK];             // 1 MB
__device__ __align__(16) __half g_tmph[(size_t)BB * SEQ * KK];       // 32 MB
__device__ __align__(16) __half g_wp[(size_t)DIM * KK];              // 256 KB
__device__ float g_kv[BB * NH * HD * HD];
__device__ float g_km[BB * NH * HD];
__device__ float g_vm[BB * NH * HD];

__device__ __forceinline__ float elu1(float x) { return x > 0.f ? x + 1.f : __expf(x); }

__device__ __forceinline__ uint32_t smem_u32(const void* p) {
    return (uint32_t)__cvta_generic_to_shared(p);
}
__device__ __forceinline__ void cpa16(uint32_t dst, const void* src) {
    asm volatile("cp.async.cg.shared.global [%0], [%1], 16;" :: "r"(dst), "l"(src));
}
__device__ __forceinline__ void cpa_commit() {
    asm volatile("cp.async.commit_group;" ::: "memory");
}
template <int N> __device__ __forceinline__ void cpa_wait() {
    asm volatile("cp.async.wait_group %0;" :: "n"(N) : "memory");
}
#define LDSM4(r, a) \
    asm volatile("ldmatrix.sync.aligned.m8n8.x4.shared.b16 {%0,%1,%2,%3}, [%4];" \
                 : "=r"((r)[0]), "=r"((r)[1]), "=r"((r)[2]), "=r"((r)[3]) : "r"(a))
#define MMA16816(d, a, b0, b1) \
    asm volatile("mma.sync.aligned.m16n8k16.row.col.f32.f16.f16.f32 " \
                 "{%0,%1,%2,%3},{%4,%5,%6,%7},{%8,%9},{%0,%1,%2,%3};" \
                 : "+f"((d)[0]), "+f"((d)[1]), "+f"((d)[2]), "+f"((d)[3]) \
                 : "r"((a)[0]), "r"((a)[1]), "r"((a)[2]), "r"((a)[3]), "r"(b0), "r"(b1))

// ---------------- GEMM config: 128x128 CTA, warp tile 32x64, 2 CTAs/SM ----------------
#define BM 128
#define BN 128
#define BK 64
#define NCH (KK / BK)               // 8
#define NSTG 3
#define TILEA (BM * 128)            // 16384 B
#define TILEB (BN * 128)            // 16384 B
#define STGB (TILEA + TILEB)        // 32768 B
#define GEMM_SMEM (NSTG * STGB)     // 98304 B

__device__ __forceinline__ void stage_tiles(uint32_t sb, const __half* Ab,
                                            const __half* Bb, int tid,
                                            int chunk, int buf) {
    const uint32_t ab = sb + buf * STGB;
    const uint32_t bbse = ab + TILEA;
    const __half* Ap = Ab + chunk * BK;
    const __half* Bp = Bb + chunk * BK;
#pragma unroll
    for (int i = 0; i < 4; i++) {
        int line = tid + i * 256;            // 0..1023
        int row = line >> 3, j = line & 7;
        uint32_t sw = row * 128 + ((j ^ (row & 7)) << 4);
        cpa16(ab + sw, Ap + (size_t)row * KK + j * 8);
    }
#pragma unroll
    for (int i = 0; i < 4; i++) {
        int line = tid + i * 256;
        int row = line >> 3, j = line & 7;
        uint32_t sw = row * 128 + ((j ^ (row & 7)) << 4);
        cpa16(bbse + sw, Bp + (size_t)row * KK + j * 8);
    }
    cpa_commit();
}

// C[M,Nn] = A'[M,512]h @ B'[Nn,512]h^T + bias (fp32 accum)
__global__ __launch_bounds__(256, 2)
void gemm_half(const __half* __restrict__ A, const __half* __restrict__ Bm,
               const float* __restrict__ bias, float* __restrict__ C, int Nn) {
    extern __shared__ char smem[];
    const uint32_t sb = smem_u32(smem);
    const int tid = threadIdx.x;
    const int wid = tid >> 5;
    const int lane = tid & 31;
    const int bm = blockIdx.y * BM;
    const int bn = blockIdx.x * BN;
    const int wm0 = (wid & 3) * 32;          // 4 warps in M
    const int wn0 = (wid >> 2) * 64;         // 2 warps in N

    const __half* Ab = A + (size_t)bm * KK;
    const __half* Bb = Bm + (size_t)bn * KK;

    float acc[2][8][4];
#pragma unroll
    for (int i = 0; i < 2; i++)
#pragma unroll
        for (int j = 0; j < 8; j++)
#pragma unroll
            for (int k = 0; k < 4; k++) acc[i][j][k] = 0.f;

    const int lrA = (lane & 7) + ((lane >> 3) & 1) * 8;
    const int lcA = ((lane >> 4) & 1) * 16;
    const int lrB = ((lane >> 4) & 1) * 8 + (lane & 7);
    const int lcB = ((lane >> 3) & 1) * 16;

    stage_tiles(sb, Ab, Bb, tid, 0, 0);
    stage_tiles(sb, Ab, Bb, tid, 1, 1);

    for (int c = 0; c < NCH; c++) {
        if (c + 2 < NCH) cpa_wait<1>(); else cpa_wait<0>();
        __syncthreads();
        if (c + 2 < NCH) stage_tiles(sb, Ab, Bb, tid, c + 2, (c + 2) % NSTG);
        const uint32_t ab = sb + (c % NSTG) * STGB;
        const uint32_t bbse = ab + TILEA;
#pragma unroll
        for (int ks = 0; ks < 4; ks++) {
            uint32_t afr[2][4], bfr[4][4];
#pragma unroll
            for (int mi = 0; mi < 2; mi++) {
                int r = wm0 + mi * 16 + lrA;
                uint32_t cc = (uint32_t)(ks * 32 + lcA);
                LDSM4(afr[mi], ab + r * 128 + (cc ^ ((r & 7) << 4)));
            }
#pragma unroll
            for (int bi = 0; bi < 4; bi++) {
                int r = wn0 + bi * 16 + lrB;
                uint32_t cc = (uint32_t)(ks * 32 + lcB);
                LDSM4(bfr[bi], bbse + r * 128 + (cc ^ ((r & 7) << 4)));
            }
#pragma unroll
            for (int mi = 0; mi < 2; mi++)
#pragma unroll
                for (int nj = 0; nj < 8; nj++)
                    MMA16816(acc[mi][nj], afr[mi],
                             bfr[nj >> 1][(nj & 1) * 2], bfr[nj >> 1][(nj & 1) * 2 + 1]);
        }
    }

    const int g = lane >> 2, t4 = lane & 3;
#pragma unroll
    for (int mi = 0; mi < 2; mi++) {
#pragma unroll
        for (int nj = 0; nj < 8; nj++) {
            const int col = bn + wn0 + nj * 8 + t4 * 2;
            const float2 bv = *(const float2*)(bias + col);
            const int row0 = bm + wm0 + mi * 16 + g;
            float2 o0 = {acc[mi][nj][0] + bv.x, acc[mi][nj][1] + bv.y};
            float2 o1 = {acc[mi][nj][2] + bv.x, acc[mi][nj][3] + bv.y};
            *(float2*)(C + (size_t)row0 * Nn + col) = o0;
            *(float2*)(C + (size_t)(row0 + 8) * Nn + col) = o1;
        }
    }
}

// ---------------- fused prep: all splits + accumulator zeroing, one launch ----------------
#define TX (BB * SEQ * DIM)         // 8388608
#define TW (QKVO * DIM)             // 262144
#define TP (DIM * DIM)              // 65536
#define NKV (BB * NH * HD * HD)     // 32768
#define NKM (BB * NH * HD)          // 1024
#define TTOT (TX + TW + TP + NKV + 2 * NKM)

__global__ void prep_kernel(const float* __restrict__ x,
                            const float* __restrict__ W_qkvo,
                            const float* __restrict__ W_proj) {
    int i = blockIdx.x * 256 + threadIdx.x;
    if (i >= TTOT) return;
    if (i < TX) {
        int row = i >> 8, c = i & 255;
        float v = x[i];
        __half hi = __float2half_rn(v);
        __half lo = __float2half_rn(v - __half2float(hi));
        size_t base = (size_t)row * KK + c;
        g_xs[base] = hi;
        g_xs[base + 256] = lo;               // A operand: [hi | lo]
    } else if (i < TX + TW) {
        int k = i - TX;
        int row = k >> 8, c = k & 255;
        float v = W_qkvo[k];
        __half hi = __float2half_rn(v);
        size_t base = (size_t)row * KK + c;
        g_ws[base] = hi;
        g_ws[base + 256] = hi;               // B operand: [hi | hi]
    } else if (i < TX + TW + TP) {
        int k = i - TX - TW;
        int row = k >> 8, c = k & 255;
        float v = W_proj[k];
        __half hi = __float2half_rn(v);
        size_t base = (size_t)row * KK + c;
        g_wp[base] = hi;
        g_wp[base + 256] = hi;
    } else {
        int k = i - TX - TW - TP;
        if (k < NKV) g_kv[k] = 0.f;
        else if (k < NKV + NKM) g_km[k - NKV] = 0.f;
        else g_vm[k - NKV - NKM] = 0.f;
    }
}

// ---------------- per-(b,h) state reduction: double-buffered, 1 sync / 8 tokens ----------
#define CHUNK 512
#define NIT (CHUNK / 8)
__global__ __launch_bounds__(256)
void reduce_kernel(const float* __restrict__ sinp, const float* __restrict__ cosp) {
    const int bh = blockIdx.x;
    const int chunk = blockIdx.y;
    const int b = bh / NH, h = bh % NH;
    const int tid = threadIdx.x;
    const int j = tid >> 5;                  // token sub 0..7
    const int d = tid & 31;
    const int dbase = j * 4;
    __shared__ float s_ks[2][8][32];
    __shared__ float s_vs[2][8][32];
    float acc[4] = {0.f, 0.f, 0.f, 0.f};
    float ksum = 0.f, vsum = 0.f;
    const int n0 = chunk * CHUNK;
    const float sgn = (d & 1) ? 1.f : -1.f;
    const size_t kcol = INTERNAL + h * HD;
    const size_t vcol = 2 * INTERNAL + h * HD;

    // prologue: load+convert iteration 0 into buffer 0
    {
        const int n = n0 + j;
        const size_t row = ((size_t)b * SEQ + n) * QKVO;
        const float kh  = elu1(g_qkvo[row + kcol + d]);
        const float khp = elu1(g_qkvo[row + kcol + (d ^ 1)]);
        const float vv  = g_qkvo[row + vcol + d];
        const float sn = sinp[n * HD + d];
        const float cs = cosp[n * HD + d];
        s_ks[0][j][d] = (kh * cs + sgn * khp * sn) * S_CONST;
        s_vs[0][j][d] = vv * S_CONST;
        ksum += kh;
        vsum += vv;
    }
    __syncthreads();

    for (int it = 0; it < NIT; it++) {
        const int bsel = it & 1;
        float nk = 0.f, nkp = 0.f, nv = 0.f, nsn = 0.f, ncs = 0.f;
        const bool more = (it + 1 < NIT);
        if (more) {
            const int n = n0 + (it + 1) * 8 + j;
            const size_t row = ((size_t)b * SEQ + n) * QKVO;
            nk  = g_qkvo[row + kcol + d];
            nkp = g_qkvo[row + kcol + (d ^ 1)];
            nv  = g_qkvo[row + vcol + d];
            nsn = sinp[n * HD + d];
            ncs = cosp[n * HD + d];
        }
#pragma unroll
        for (int jj = 0; jj < 8; jj++) {
            const float vv = s_vs[bsel][jj][d];
#pragma unroll
            for (int dd = 0; dd < 4; dd++)
                acc[dd] += s_ks[bsel][jj][dbase + dd] * vv;
        }
        if (more) {
            const float kh = elu1(nk);
            const float khp = elu1(nkp);
            s_ks[bsel ^ 1][j][d] = (kh * ncs + sgn * khp * nsn) * S_CONST;
            s_vs[bsel ^ 1][j][d] = nv * S_CONST;
            ksum += kh;
            vsum += nv;
        }
        __syncthreads();
    }
#pragma unroll
    for (int dd = 0; dd < 4; dd++)
        atomicAdd(&g_kv[(bh * HD + dbase + dd) * HD + d], acc[dd]);
    atomicAdd(&g_km[bh * HD + d], ksum);
    atomicAdd(&g_vm[bh * HD + d], vsum);
}

// ---------------- attn epilogue: thread-per-(token,head), zero shuffles ----------------
#define ATB 256
__global__ __launch_bounds__(256)
void attn_kernel(const float* __restrict__ sinp, const float* __restrict__ cosp,
                 const float* __restrict__ W_lepe, const float* __restrict__ b_lepe) {
    const int b = blockIdx.y;
    const int h = blockIdx.z;
    const int n = blockIdx.x * ATB + threadIdx.x;
    const int bh = b * NH + h;
    __shared__ __align__(16) float s_kv[HD][HD];
    __shared__ float s_km[HD], s_vm[HD], s_w0[HD], s_w1[HD], s_w2[HD], s_bl[HD];

    for (int i = threadIdx.x; i < HD * HD; i += 256)
        ((float*)s_kv)[i] = g_kv[bh * HD * HD + i];
    if (threadIdx.x < HD) {
        const int c = h * HD + threadIdx.x;
        const float invN = 1.f / (float)SEQ;
        s_km[threadIdx.x] = g_km[bh * HD + threadIdx.x] * invN;
        s_vm[threadIdx.x] = g_vm[bh * HD + threadIdx.x] * invN;
        s_w0[threadIdx.x] = W_lepe[c * 3 + 0];
        s_w1[threadIdx.x] = W_lepe[c * 3 + 1];
        s_w2[threadIdx.x] = W_lepe[c * 3 + 2];
        s_bl[threadIdx.x] = b_lepe[c];
    }
    __syncthreads();

    const size_t row = ((size_t)b * SEQ + n) * QKVO;
    const int cb = h * HD;

    float qh[HD];
#pragma unroll
    for (int d4 = 0; d4 < 8; d4++) {
        float4 v = *(const float4*)(g_qkvo + row + cb + d4 * 4);
        qh[d4 * 4 + 0] = elu1(v.x);
        qh[d4 * 4 + 1] = elu1(v.y);
        qh[d4 * 4 + 2] = elu1(v.z);
        qh[d4 * 4 + 3] = elu1(v.w);
    }
    float z = 0.f;
#pragma unroll
    for (int d = 0; d < HD; d++) z += qh[d] * s_km[d];
    z *= SCALE_F;

#pragma unroll
    for (int d4 = 0; d4 < 8; d4++) {
        float4 sn = *(const float4*)(sinp + (size_t)n * HD + d4 * 4);
        float4 cs = *(const float4*)(cosp + (size_t)n * HD + d4 * 4);
        const float a0 = qh[d4 * 4 + 0], a1 = qh[d4 * 4 + 1];
        const float a2 = qh[d4 * 4 + 2], a3 = qh[d4 * 4 + 3];
        qh[d4 * 4 + 0] = a0 * cs.x - a1 * sn.x;
        qh[d4 * 4 + 1] = a1 * cs.y + a0 * sn.y;
        qh[d4 * 4 + 2] = a2 * cs.z - a3 * sn.z;
        qh[d4 * 4 + 3] = a3 * cs.w + a2 * sn.w;
    }

    float acc[HD];
#pragma unroll
    for (int e = 0; e < HD; e++) acc[e] = 0.f;
#pragma unroll
    for (int d = 0; d < HD; d++) {
        const float qd = qh[d];
        const float4* kvr = (const float4*)s_kv[d];
#pragma unroll
        for (int e4 = 0; e4 < 8; e4++) {
            float4 kv4 = kvr[e4];
            acc[e4 * 4 + 0] += qd * kv4.x;
            acc[e4 * 4 + 1] += qd * kv4.y;
            acc[e4 * 4 + 2] += qd * kv4.z;
            acc[e4 * 4 + 3] += qd * kv4.w;
        }
    }

    const float zf = 1.f + 1.f / (z + 1e-6f);
    const bool hp = (n > 0), hn = (n < SEQ - 1);
    const float* vrow = g_qkvo + row + 2 * INTERNAL + cb;
    const float* orow = g_qkvo + row + 3 * INTERNAL + cb;
    __half* outp = g_tmph + ((size_t)b * SEQ + n) * KK + cb;

#pragma unroll
    for (int e4 = 0; e4 < 8; e4++) {
        const float4 v0 = *(const float4*)(vrow + e4 * 4);
        const float4 vp = hp ? *(const float4*)(vrow - QKVO + e4 * 4) : make_float4(0, 0, 0, 0);
        const float4 vn = hn ? *(const float4*)(vrow + QKVO + e4 * 4) : make_float4(0, 0, 0, 0);
        const float4 og = *(const float4*)(orow + e4 * 4);
        const int e = e4 * 4;
        float r0 = (acc[e + 0] * zf - z * s_vm[e + 0]
                    + vp.x * s_w0[e + 0] + v0.x * s_w1[e + 0] + vn.x * s_w2[e + 0] + s_bl[e + 0]) * og.x;
        float r1 = (acc[e + 1] * zf - z * s_vm[e + 1]
                    + vp.y * s_w0[e + 1] + v0.y * s_w1[e + 1] + vn.y * s_w2[e + 1] + s_bl[e + 1]) * og.y;
        float r2 = (acc[e + 2] * zf - z * s_vm[e + 2]
                    + vp.z * s_w0[e + 2] + v0.z * s_w1[e + 2] + vn.z * s_w2[e + 2] + s_bl[e + 2]) * og.z;
        float r3 = (acc[e + 3] * zf - z * s_vm[e + 3]
                    + vp.w * s_w0[e + 3] + v0.w * s_w1[e + 3] + vn.w * s_w2[e + 3] + s_bl[e + 3]) * og.w;
        __half h0 = __float2half_rn(r0), h1 = __float2half_rn(r1);
        __half h2 = __float2half_rn(r2), h3 = __float2half_rn(r3);
        __half l0 = __float2half_rn(r0 - __half2float(h0));
        __half l1 = __float2half_rn(r1 - __half2float(h1));
        __half l2 = __float2half_rn(r2 - __half2float(h2));
        __half l3 = __float2half_rn(r3 - __half2float(h3));
        uint2 hw, lw;
        hw.x = ((uint32_t)__half_as_ushort(h1) << 16) | __half_as_ushort(h0);
        hw.y = ((uint32_t)__half_as_ushort(h3) << 16) | __half_as_ushort(h2);
        lw.x = ((uint32_t)__half_as_ushort(l1) << 16) | __half_as_ushort(l0);
        lw.y = ((uint32_t)__half_as_ushort(l3) << 16) | __half_as_ushort(l2);
        *(uint2*)(outp + e) = hw;
        *(uint2*)(outp + 256 + e) = lw;
    }
}

// ---------------- launch ----------------
extern "C" void kernel_launch(void* const* d_in, const int* in_sizes, int n_in,
                              void* d_out, int out_size) {
    const float* x      = (const float*)d_in[0];
    const float* sinp   = (const float*)d_in[1];
    const float* cosp   = (const float*)d_in[2];
    const float* W_qkvo = (const float*)d_in[3];
    const float* b_qkvo = (const float*)d_in[4];
    const float* W_lepe = (const float*)d_in[5];
    const float* b_lepe = (const float*)d_in[6];
    const float* W_proj = (const float*)d_in[7];
    const float* b_proj = (const float*)d_in[8];
    float* out = (float*)d_out;

    __half *xs_p, *ws_p, *tmph_p, *wp_p;
    float* qkvo_p;
    cudaGetSymbolAddress((void**)&qkvo_p, g_qkvo);
    cudaGetSymbolAddress((void**)&xs_p, g_xs);
    cudaGetSymbolAddress((void**)&ws_p, g_ws);
    cudaGetSymbolAddress((void**)&tmph_p, g_tmph);
    cudaGetSymbolAddress((void**)&wp_p, g_wp);

    cudaFuncSetAttribute(gemm_half, cudaFuncAttributeMaxDynamicSharedMemorySize, GEMM_SMEM);

    const int M = BB * SEQ;  // 32768

    // 0) fused splits + zeroing, one launch
    prep_kernel<<<(TTOT + 255) / 256, 256>>>(x, W_qkvo, W_proj);

    // 1) qkvo = x @ W_qkvo^T + b  (HMMA, K=512 split)
    {
        dim3 grid(QKVO / BN, M / BM);
        gemm_half<<<grid, 256, GEMM_SMEM>>>(xs_p, ws_p, b_qkvo, qkvo_p, QKVO);
    }
    // 2) state reduction
    {
        dim3 grid(BB * NH, SEQ / CHUNK);
        reduce_kernel<<<grid, 256>>>(sinp, cosp);
    }
    // 3) attention epilogue
    {
        dim3 grid(SEQ / ATB, BB, NH);
        attn_kernel<<<grid, 256>>>(sinp, cosp, W_lepe, b_lepe);
    }
    // 4) out = tmp @ W_proj^T + b_proj  (HMMA)
    {
        dim3 grid(DIM / BN, M / BM);
        gemm_half<<<grid, 256, GEMM_SMEM>>>(tmph_p, wp_p, b_proj, out, DIM);
    }
}